// round 1
// baseline (speedup 1.0000x reference)
#include <cuda_runtime.h>
#include <math.h>

#define BATCH   8
#define SEQ     1024
#define DMODEL  768
#define NHEAD   12
#define DHEAD   64
#define MTOT    (BATCH * SEQ)   // 8192

// ---------------------------------------------------------------------------
// Scratch (device globals — no allocation allowed)
// ---------------------------------------------------------------------------
__device__ float g_Q [MTOT * DMODEL];
__device__ float g_K [MTOT * DMODEL];
__device__ float g_V [MTOT * DMODEL];
__device__ float g_AO[MTOT * DMODEL];

// ---------------------------------------------------------------------------
// GEMM (NT): C[M,N] = A[M,K] @ B[N,K]^T  (+ bias[N] if bias != nullptr)
// 128x128 block tile, BK=8, 256 threads, 8x8 per-thread microtile.
// M % 128 == 0, N % 128 == 0, K % 8 == 0 (true for all our shapes).
// ---------------------------------------------------------------------------
__global__ __launch_bounds__(256) void gemm_nt_kernel(
    const float* __restrict__ A, const float* __restrict__ B,
    const float* __restrict__ bias, float* __restrict__ C,
    int M, int N, int K)
{
    __shared__ float As[8][128];
    __shared__ float Bs[8][128];

    const int tid = threadIdx.x;
    const int tx  = tid & 15;          // 0..15 -> col group
    const int ty  = tid >> 4;          // 0..15 -> row group
    const int rowBase = blockIdx.y * 128;
    const int colBase = blockIdx.x * 128;

    // loader: each thread loads one float4 of A and one of B per BK step
    const int lr = tid >> 1;           // 0..127  (tile row)
    const int ls = (tid & 1) * 4;      // 0 or 4  (k offset)
    const float* Ap = A + (size_t)(rowBase + lr) * K + ls;
    const float* Bp = B + (size_t)(colBase + lr) * K + ls;

    float acc[8][8];
    #pragma unroll
    for (int i = 0; i < 8; i++)
        #pragma unroll
        for (int j = 0; j < 8; j++) acc[i][j] = 0.f;

    for (int k0 = 0; k0 < K; k0 += 8) {
        float4 a4 = *(const float4*)(Ap + k0);
        float4 b4 = *(const float4*)(Bp + k0);
        As[ls + 0][lr] = a4.x; As[ls + 1][lr] = a4.y;
        As[ls + 2][lr] = a4.z; As[ls + 3][lr] = a4.w;
        Bs[ls + 0][lr] = b4.x; Bs[ls + 1][lr] = b4.y;
        Bs[ls + 2][lr] = b4.z; Bs[ls + 3][lr] = b4.w;
        __syncthreads();

        #pragma unroll
        for (int k = 0; k < 8; k++) {
            float ra[8], rb[8];
            #pragma unroll
            for (int i = 0; i < 8; i++) ra[i] = As[k][ty * 8 + i];
            #pragma unroll
            for (int j = 0; j < 8; j++) rb[j] = Bs[k][tx * 8 + j];
            #pragma unroll
            for (int i = 0; i < 8; i++)
                #pragma unroll
                for (int j = 0; j < 8; j++)
                    acc[i][j] = fmaf(ra[i], rb[j], acc[i][j]);
        }
        __syncthreads();
    }

    #pragma unroll
    for (int i = 0; i < 8; i++) {
        const int r = rowBase + ty * 8 + i;
        float* Crow = C + (size_t)r * N + colBase + tx * 8;
        #pragma unroll
        for (int j = 0; j < 8; j++) {
            float v = acc[i][j];
            if (bias) v += bias[colBase + tx * 8 + j];
            Crow[j] = v;
        }
    }
}

// ---------------------------------------------------------------------------
// Flash attention: per (b,h), 64-row query tiles, online softmax over 64-col
// key chunks. Q/K/V in [B, SEQ, DMODEL] layout, head h = cols [h*64, h*64+64).
// Block: 256 threads. grid = (SEQ/64, BATCH*NHEAD).
// ---------------------------------------------------------------------------
#define ATT_BM 64
#define ATT_BN 64
#define ATT_LD 68      // DHEAD + 4 pad (keeps float4 smem stores 16B-aligned)

__global__ __launch_bounds__(256) void attn_kernel(
    const float* __restrict__ Q, const float* __restrict__ K,
    const float* __restrict__ V, float* __restrict__ O)
{
    extern __shared__ float sm[];
    float* Qs   = sm;                       // 64 x 68
    float* Ks   = Qs + ATT_BM * ATT_LD;     // 64 x 68
    float* Vs   = Ks + ATT_BN * ATT_LD;     // 64 x 68
    float* Ss   = Vs + ATT_BN * ATT_LD;     // 64 x 68 (scores / probs)
    float* mrow = Ss + ATT_BM * ATT_LD;     // 64
    float* lrow = mrow + ATT_BM;            // 64
    float* arow = lrow + ATT_BM;            // 64

    const int tid = threadIdx.x;
    const int bh  = blockIdx.y;
    const int b   = bh / NHEAD;
    const int h   = bh % NHEAD;
    const int q0  = blockIdx.x * ATT_BM;

    const float* Qg = Q + (size_t)b * SEQ * DMODEL + h * DHEAD;
    const float* Kg = K + (size_t)b * SEQ * DMODEL + h * DHEAD;
    const float* Vg = V + (size_t)b * SEQ * DMODEL + h * DHEAD;

    // load Q tile (64 rows x 64 cols = 1024 float4)
    for (int it = tid; it < ATT_BM * 16; it += 256) {
        const int r = it >> 4, c4 = (it & 15) * 4;
        *(float4*)(Qs + r * ATT_LD + c4) =
            *(const float4*)(Qg + (size_t)(q0 + r) * DMODEL + c4);
    }
    if (tid < ATT_BM) { mrow[tid] = -1e30f; lrow[tid] = 0.f; }

    const int tx = tid & 15, ty = tid >> 4;
    const int rb = ty * 4, cb = tx * 4;      // 4x4 microtile
    float acc[4][4] = {};
    const float scale = 0.125f;              // 1/sqrt(64)

    for (int k0 = 0; k0 < SEQ; k0 += ATT_BN) {
        __syncthreads();   // smem reuse fence (also covers Q load on iter 0)
        for (int it = tid; it < ATT_BN * 16; it += 256) {
            const int r = it >> 4, c4 = (it & 15) * 4;
            *(float4*)(Ks + r * ATT_LD + c4) =
                *(const float4*)(Kg + (size_t)(k0 + r) * DMODEL + c4);
            *(float4*)(Vs + r * ATT_LD + c4) =
                *(const float4*)(Vg + (size_t)(k0 + r) * DMODEL + c4);
        }
        __syncthreads();

        // S = scale * Q @ K^T   (each thread: 4x4 of the 64x64 tile)
        float s[4][4] = {};
        #pragma unroll
        for (int d = 0; d < DHEAD; d++) {
            float qv[4], kv[4];
            #pragma unroll
            for (int i = 0; i < 4; i++) qv[i] = Qs[(rb + i) * ATT_LD + d];
            #pragma unroll
            for (int j = 0; j < 4; j++) kv[j] = Ks[(cb + j) * ATT_LD + d];
            #pragma unroll
            for (int i = 0; i < 4; i++)
                #pragma unroll
                for (int j = 0; j < 4; j++)
                    s[i][j] = fmaf(qv[i], kv[j], s[i][j]);
        }
        #pragma unroll
        for (int i = 0; i < 4; i++)
            #pragma unroll
            for (int j = 0; j < 4; j++)
                Ss[(rb + i) * ATT_LD + cb + j] = s[i][j] * scale;
        __syncthreads();

        // online softmax row update (one thread per row)
        if (tid < ATT_BM) {
            float* srow = Ss + tid * ATT_LD;
            float mo = mrow[tid], mx = mo;
            #pragma unroll 8
            for (int j = 0; j < ATT_BN; j++) mx = fmaxf(mx, srow[j]);
            float sum = 0.f;
            #pragma unroll 8
            for (int j = 0; j < ATT_BN; j++) {
                float p = __expf(srow[j] - mx);
                srow[j] = p; sum += p;
            }
            const float a = __expf(mo - mx);
            arow[tid] = a;
            mrow[tid] = mx;
            lrow[tid] = lrow[tid] * a + sum;
        }
        __syncthreads();

        // acc = acc * alpha[row] + P @ V
        float av[4];
        #pragma unroll
        for (int i = 0; i < 4; i++) av[i] = arow[rb + i];
        #pragma unroll
        for (int i = 0; i < 4; i++)
            #pragma unroll
            for (int j = 0; j < 4; j++) acc[i][j] *= av[i];
        #pragma unroll
        for (int jj = 0; jj < ATT_BN; jj++) {
            float pv[4], vv[4];
            #pragma unroll
            for (int i = 0; i < 4; i++) pv[i] = Ss[(rb + i) * ATT_LD + jj];
            #pragma unroll
            for (int j = 0; j < 4; j++) vv[j] = Vs[jj * ATT_LD + cb + j];
            #pragma unroll
            for (int i = 0; i < 4; i++)
                #pragma unroll
                for (int j = 0; j < 4; j++)
                    acc[i][j] = fmaf(pv[i], vv[j], acc[i][j]);
        }
    }

    // final normalize + store (lrow writes were fenced by in-loop syncthreads)
    float linv[4];
    #pragma unroll
    for (int i = 0; i < 4; i++) linv[i] = 1.f / lrow[rb + i];
    float* Og = O + (size_t)b * SEQ * DMODEL + h * DHEAD;
    #pragma unroll
    for (int i = 0; i < 4; i++)
        #pragma unroll
        for (int j = 0; j < 4; j++)
            Og[(size_t)(q0 + rb + i) * DMODEL + cb + j] = acc[i][j] * linv[i];
}

// ---------------------------------------------------------------------------
// Launch
// ---------------------------------------------------------------------------
extern "C" void kernel_launch(void* const* d_in, const int* in_sizes, int n_in,
                              void* d_out, int out_size)
{
    const float* z   = (const float*)d_in[0];
    const float* w_q = (const float*)d_in[1];
    const float* w_k = (const float*)d_in[2];
    const float* w_v = (const float*)d_in[3];
    const float* w_o = (const float*)d_in[4];
    const float* b_o = (const float*)d_in[5];
    float* out = (float*)d_out;

    float *Qp, *Kp, *Vp, *AOp;
    cudaGetSymbolAddress((void**)&Qp,  g_Q);
    cudaGetSymbolAddress((void**)&Kp,  g_K);
    cudaGetSymbolAddress((void**)&Vp,  g_V);
    cudaGetSymbolAddress((void**)&AOp, g_AO);

    const dim3 gemmGrid(DMODEL / 128, MTOT / 128);   // (6, 64)

    gemm_nt_kernel<<<gemmGrid, 256>>>(z, w_q, nullptr, Qp, MTOT, DMODEL, DMODEL);
    gemm_nt_kernel<<<gemmGrid, 256>>>(z, w_k, nullptr, Kp, MTOT, DMODEL, DMODEL);
    gemm_nt_kernel<<<gemmGrid, 256>>>(z, w_v, nullptr, Vp, MTOT, DMODEL, DMODEL);

    const int attnSmem = (4 * ATT_BM * ATT_LD + 3 * ATT_BM) * (int)sizeof(float);
    static bool attrSet = false;
    if (!attrSet) {
        cudaFuncSetAttribute(attn_kernel,
                             cudaFuncAttributeMaxDynamicSharedMemorySize,
                             attnSmem);
        attrSet = true;
    }
    attn_kernel<<<dim3(SEQ / ATT_BM, BATCH * NHEAD), 256, attnSmem>>>(Qp, Kp, Vp, AOp);

    gemm_nt_kernel<<<gemmGrid, 256>>>(AOp, w_o, b_o, out, MTOT, DMODEL, DMODEL);
}

// round 2
// speedup vs baseline: 1.5898x; 1.5898x over previous
#include <cuda_runtime.h>
#include <math.h>
#include <stdint.h>

#define BATCH   8
#define SEQ     1024
#define DMODEL  768
#define NHEAD   12
#define DHEAD   64
#define MTOT    (BATCH * SEQ)   // 8192

// ---------------------------------------------------------------------------
// Scratch (device globals — no allocation allowed)
// ---------------------------------------------------------------------------
__device__ float g_Q [MTOT * DMODEL];
__device__ float g_K [MTOT * DMODEL];
__device__ float g_V [MTOT * DMODEL];
__device__ float g_AO[MTOT * DMODEL];

// ---------------------------------------------------------------------------
// TF32 helpers
// ---------------------------------------------------------------------------
__device__ __forceinline__ uint32_t f2tf32(float x) {
    uint32_t y;
    asm("cvt.rna.tf32.f32 %0, %1;" : "=r"(y) : "f"(x));
    return y;
}

__device__ __forceinline__ void mma_tf32(float c[4],
    uint32_t a0, uint32_t a1, uint32_t a2, uint32_t a3,
    uint32_t b0, uint32_t b1)
{
    asm volatile(
        "mma.sync.aligned.m16n8k8.row.col.f32.tf32.tf32.f32 "
        "{%0,%1,%2,%3}, {%4,%5,%6,%7}, {%8,%9}, {%0,%1,%2,%3};"
        : "+f"(c[0]), "+f"(c[1]), "+f"(c[2]), "+f"(c[3])
        : "r"(a0), "r"(a1), "r"(a2), "r"(a3), "r"(b0), "r"(b1));
}

// ---------------------------------------------------------------------------
// TF32 tensor-core GEMM (NT): C[M,N] = A[M,K] @ B[N,K]^T (+ bias[N])
// 128x128 block tile, BK=32, 256 threads (8 warps), warp tile 64x32.
// Requires M%128==0, N%128==0, K%32==0.
// ---------------------------------------------------------------------------
#define GSTRIDE 36   // smem row stride (floats): bank = (4*row + col) % 32

__global__ __launch_bounds__(256) void gemm_tf32_kernel(
    const float* __restrict__ A, const float* __restrict__ B,
    const float* __restrict__ bias, float* __restrict__ C,
    int M, int N, int K)
{
    __shared__ uint32_t As[128 * GSTRIDE];
    __shared__ uint32_t Bs[128 * GSTRIDE];

    const int tid  = threadIdx.x;
    const int lane = tid & 31;
    const int wid  = tid >> 5;
    const int g    = lane >> 2;   // group id (row within fragment)
    const int t    = lane & 3;    // thread-in-group (col within fragment)
    const int wm   = wid >> 2;    // 0..1 : 64-row slab
    const int wn   = wid & 3;     // 0..3 : 32-col slab

    const int rowBase = blockIdx.y * 128;
    const int colBase = blockIdx.x * 128;

    // staging: each thread owns 4 float4 of A and 4 of B per BK=32 tile
    float4 aST[4], bST[4];
    // element id for f4 #i : id = tid + i*256 ; row = id>>3 ; c4 = (id&7)*4
    const float* Ag = A + (size_t)rowBase * K;
    const float* Bg = B + (size_t)colBase * K;

    #pragma unroll
    for (int i = 0; i < 4; i++) {
        const int id = tid + i * 256;
        const int r  = id >> 3, c4 = (id & 7) * 4;
        aST[i] = *(const float4*)(Ag + (size_t)r * K + c4);
        bST[i] = *(const float4*)(Bg + (size_t)r * K + c4);
    }

    float acc[4][4][4];
    #pragma unroll
    for (int mi = 0; mi < 4; mi++)
        #pragma unroll
        for (int ni = 0; ni < 4; ni++)
            #pragma unroll
            for (int q = 0; q < 4; q++) acc[mi][ni][q] = 0.f;

    const int nIter = K / 32;
    for (int it = 0; it < nIter; it++) {
        // commit staged regs -> smem (with RNA tf32 conversion)
        #pragma unroll
        for (int i = 0; i < 4; i++) {
            const int id = tid + i * 256;
            const int r  = id >> 3, c4 = (id & 7) * 4;
            uint32_t* as = As + r * GSTRIDE + c4;
            uint32_t* bs = Bs + r * GSTRIDE + c4;
            as[0] = f2tf32(aST[i].x); as[1] = f2tf32(aST[i].y);
            as[2] = f2tf32(aST[i].z); as[3] = f2tf32(aST[i].w);
            bs[0] = f2tf32(bST[i].x); bs[1] = f2tf32(bST[i].y);
            bs[2] = f2tf32(bST[i].z); bs[3] = f2tf32(bST[i].w);
        }
        __syncthreads();

        // prefetch next tile into regs (overlaps with compute below)
        if (it + 1 < nIter) {
            const int k0 = (it + 1) * 32;
            #pragma unroll
            for (int i = 0; i < 4; i++) {
                const int id = tid + i * 256;
                const int r  = id >> 3, c4 = (id & 7) * 4;
                aST[i] = *(const float4*)(Ag + (size_t)r * K + k0 + c4);
                bST[i] = *(const float4*)(Bg + (size_t)r * K + k0 + c4);
            }
        }

        // compute: 4 k-steps of 8
        #pragma unroll
        for (int kk = 0; kk < 32; kk += 8) {
            uint32_t af[4][4], bf[4][2];
            #pragma unroll
            for (int mi = 0; mi < 4; mi++) {
                const int rb = wm * 64 + mi * 16;
                af[mi][0] = As[(rb + g    ) * GSTRIDE + kk + t    ];
                af[mi][1] = As[(rb + g + 8) * GSTRIDE + kk + t    ];
                af[mi][2] = As[(rb + g    ) * GSTRIDE + kk + t + 4];
                af[mi][3] = As[(rb + g + 8) * GSTRIDE + kk + t + 4];
            }
            #pragma unroll
            for (int ni = 0; ni < 4; ni++) {
                const int nb = wn * 32 + ni * 8;
                bf[ni][0] = Bs[(nb + g) * GSTRIDE + kk + t    ];
                bf[ni][1] = Bs[(nb + g) * GSTRIDE + kk + t + 4];
            }
            #pragma unroll
            for (int mi = 0; mi < 4; mi++)
                #pragma unroll
                for (int ni = 0; ni < 4; ni++)
                    mma_tf32(acc[mi][ni],
                             af[mi][0], af[mi][1], af[mi][2], af[mi][3],
                             bf[ni][0], bf[ni][1]);
        }
        __syncthreads();
    }

    // epilogue: c0,c1 -> (row, 2t), (row, 2t+1) ; c2,c3 -> row+8
    #pragma unroll
    for (int mi = 0; mi < 4; mi++) {
        const int r0 = rowBase + wm * 64 + mi * 16 + g;
        #pragma unroll
        for (int ni = 0; ni < 4; ni++) {
            const int cidx = colBase + wn * 32 + ni * 8 + 2 * t;
            float b0 = 0.f, b1 = 0.f;
            if (bias) { b0 = bias[cidx]; b1 = bias[cidx + 1]; }
            float2 v01 = make_float2(acc[mi][ni][0] + b0, acc[mi][ni][1] + b1);
            float2 v23 = make_float2(acc[mi][ni][2] + b0, acc[mi][ni][3] + b1);
            *(float2*)(C + (size_t)r0 * N + cidx)       = v01;
            *(float2*)(C + (size_t)(r0 + 8) * N + cidx) = v23;
        }
    }
}

// ---------------------------------------------------------------------------
// Flash attention (fp32, unchanged from R1): per (b,h), 64-row query tiles.
// ---------------------------------------------------------------------------
#define ATT_BM 64
#define ATT_BN 64
#define ATT_LD 68

__global__ __launch_bounds__(256) void attn_kernel(
    const float* __restrict__ Q, const float* __restrict__ K,
    const float* __restrict__ V, float* __restrict__ O)
{
    extern __shared__ float sm[];
    float* Qs   = sm;
    float* Ks   = Qs + ATT_BM * ATT_LD;
    float* Vs   = Ks + ATT_BN * ATT_LD;
    float* Ss   = Vs + ATT_BN * ATT_LD;
    float* mrow = Ss + ATT_BM * ATT_LD;
    float* lrow = mrow + ATT_BM;
    float* arow = lrow + ATT_BM;

    const int tid = threadIdx.x;
    const int bh  = blockIdx.y;
    const int b   = bh / NHEAD;
    const int h   = bh % NHEAD;
    const int q0  = blockIdx.x * ATT_BM;

    const float* Qg = Q + (size_t)b * SEQ * DMODEL + h * DHEAD;
    const float* Kg = K + (size_t)b * SEQ * DMODEL + h * DHEAD;
    const float* Vg = V + (size_t)b * SEQ * DMODEL + h * DHEAD;

    for (int it = tid; it < ATT_BM * 16; it += 256) {
        const int r = it >> 4, c4 = (it & 15) * 4;
        *(float4*)(Qs + r * ATT_LD + c4) =
            *(const float4*)(Qg + (size_t)(q0 + r) * DMODEL + c4);
    }
    if (tid < ATT_BM) { mrow[tid] = -1e30f; lrow[tid] = 0.f; }

    const int tx = tid & 15, ty = tid >> 4;
    const int rb = ty * 4, cb = tx * 4;
    float acc[4][4] = {};
    const float scale = 0.125f;

    for (int k0 = 0; k0 < SEQ; k0 += ATT_BN) {
        __syncthreads();
        for (int it = tid; it < ATT_BN * 16; it += 256) {
            const int r = it >> 4, c4 = (it & 15) * 4;
            *(float4*)(Ks + r * ATT_LD + c4) =
                *(const float4*)(Kg + (size_t)(k0 + r) * DMODEL + c4);
            *(float4*)(Vs + r * ATT_LD + c4) =
                *(const float4*)(Vg + (size_t)(k0 + r) * DMODEL + c4);
        }
        __syncthreads();

        float s[4][4] = {};
        #pragma unroll
        for (int d = 0; d < DHEAD; d++) {
            float qv[4], kv[4];
            #pragma unroll
            for (int i = 0; i < 4; i++) qv[i] = Qs[(rb + i) * ATT_LD + d];
            #pragma unroll
            for (int j = 0; j < 4; j++) kv[j] = Ks[(cb + j) * ATT_LD + d];
            #pragma unroll
            for (int i = 0; i < 4; i++)
                #pragma unroll
                for (int j = 0; j < 4; j++)
                    s[i][j] = fmaf(qv[i], kv[j], s[i][j]);
        }
        #pragma unroll
        for (int i = 0; i < 4; i++)
            #pragma unroll
            for (int j = 0; j < 4; j++)
                Ss[(rb + i) * ATT_LD + cb + j] = s[i][j] * scale;
        __syncthreads();

        if (tid < ATT_BM) {
            float* srow = Ss + tid * ATT_LD;
            float mo = mrow[tid], mx = mo;
            #pragma unroll 8
            for (int j = 0; j < ATT_BN; j++) mx = fmaxf(mx, srow[j]);
            float sum = 0.f;
            #pragma unroll 8
            for (int j = 0; j < ATT_BN; j++) {
                float p = __expf(srow[j] - mx);
                srow[j] = p; sum += p;
            }
            const float a = __expf(mo - mx);
            arow[tid] = a;
            mrow[tid] = mx;
            lrow[tid] = lrow[tid] * a + sum;
        }
        __syncthreads();

        float av[4];
        #pragma unroll
        for (int i = 0; i < 4; i++) av[i] = arow[rb + i];
        #pragma unroll
        for (int i = 0; i < 4; i++)
            #pragma unroll
            for (int j = 0; j < 4; j++) acc[i][j] *= av[i];
        #pragma unroll
        for (int jj = 0; jj < ATT_BN; jj++) {
            float pv[4], vv[4];
            #pragma unroll
            for (int i = 0; i < 4; i++) pv[i] = Ss[(rb + i) * ATT_LD + jj];
            #pragma unroll
            for (int j = 0; j < 4; j++) vv[j] = Vs[jj * ATT_LD + cb + j];
            #pragma unroll
            for (int i = 0; i < 4; i++)
                #pragma unroll
                for (int j = 0; j < 4; j++)
                    acc[i][j] = fmaf(pv[i], vv[j], acc[i][j]);
        }
    }

    float linv[4];
    #pragma unroll
    for (int i = 0; i < 4; i++) linv[i] = 1.f / lrow[rb + i];
    float* Og = O + (size_t)b * SEQ * DMODEL + h * DHEAD;
    #pragma unroll
    for (int i = 0; i < 4; i++)
        #pragma unroll
        for (int j = 0; j < 4; j++)
            Og[(size_t)(q0 + rb + i) * DMODEL + cb + j] = acc[i][j] * linv[i];
}

// ---------------------------------------------------------------------------
// Launch
// ---------------------------------------------------------------------------
extern "C" void kernel_launch(void* const* d_in, const int* in_sizes, int n_in,
                              void* d_out, int out_size)
{
    const float* z   = (const float*)d_in[0];
    const float* w_q = (const float*)d_in[1];
    const float* w_k = (const float*)d_in[2];
    const float* w_v = (const float*)d_in[3];
    const float* w_o = (const float*)d_in[4];
    const float* b_o = (const float*)d_in[5];
    float* out = (float*)d_out;

    float *Qp, *Kp, *Vp, *AOp;
    cudaGetSymbolAddress((void**)&Qp,  g_Q);
    cudaGetSymbolAddress((void**)&Kp,  g_K);
    cudaGetSymbolAddress((void**)&Vp,  g_V);
    cudaGetSymbolAddress((void**)&AOp, g_AO);

    const dim3 gemmGrid(DMODEL / 128, MTOT / 128);   // (6, 64)

    gemm_tf32_kernel<<<gemmGrid, 256>>>(z, w_q, nullptr, Qp, MTOT, DMODEL, DMODEL);
    gemm_tf32_kernel<<<gemmGrid, 256>>>(z, w_k, nullptr, Kp, MTOT, DMODEL, DMODEL);
    gemm_tf32_kernel<<<gemmGrid, 256>>>(z, w_v, nullptr, Vp, MTOT, DMODEL, DMODEL);

    const int attnSmem = (4 * ATT_BM * ATT_LD + 3 * ATT_BM) * (int)sizeof(float);
    static bool attrSet = false;
    if (!attrSet) {
        cudaFuncSetAttribute(attn_kernel,
                             cudaFuncAttributeMaxDynamicSharedMemorySize,
                             attnSmem);
        attrSet = true;
    }
    attn_kernel<<<dim3(SEQ / ATT_BM, BATCH * NHEAD), 256, attnSmem>>>(Qp, Kp, Vp, AOp);

    gemm_tf32_kernel<<<gemmGrid, 256>>>(AOp, w_o, b_o, out, MTOT, DMODEL, DMODEL);
}

// round 4
// speedup vs baseline: 3.6710x; 2.3091x over previous
#include <cuda_runtime.h>
#include <math.h>
#include <stdint.h>

#define BATCH   8
#define SEQ     1024
#define DMODEL  768
#define NHEAD   12
#define DHEAD   64
#define MTOT    (BATCH * SEQ)   // 8192

__device__ float g_Q [MTOT * DMODEL];
__device__ float g_K [MTOT * DMODEL];
__device__ float g_V [MTOT * DMODEL];
__device__ float g_AO[MTOT * DMODEL];

// ---------------------------------------------------------------------------
// TF32 helpers
// ---------------------------------------------------------------------------
__device__ __forceinline__ uint32_t f2tf32(float x) {
    uint32_t y;
    asm("cvt.rna.tf32.f32 %0, %1;" : "=r"(y) : "f"(x));
    return y;
}

__device__ __forceinline__ void mma_tf32(float c[4],
    uint32_t a0, uint32_t a1, uint32_t a2, uint32_t a3,
    uint32_t b0, uint32_t b1)
{
    asm volatile(
        "mma.sync.aligned.m16n8k8.row.col.f32.tf32.tf32.f32 "
        "{%0,%1,%2,%3}, {%4,%5,%6,%7}, {%8,%9}, {%0,%1,%2,%3};"
        : "+f"(c[0]), "+f"(c[1]), "+f"(c[2]), "+f"(c[3])
        : "r"(a0), "r"(a1), "r"(a2), "r"(a3), "r"(b0), "r"(b1));
}

// ---------------------------------------------------------------------------
// TF32 tensor-core GEMM (NT): C[M,N] = A[M,K] @ B[N,K]^T (+ bias[N])
// 128x128 block tile, BK=32, 256 threads (8 warps), warp tile 64x32.
// ---------------------------------------------------------------------------
#define GSTRIDE 36

__global__ __launch_bounds__(256) void gemm_tf32_kernel(
    const float* __restrict__ A, const float* __restrict__ B,
    const float* __restrict__ bias, float* __restrict__ C,
    int M, int N, int K)
{
    __shared__ uint32_t As[128 * GSTRIDE];
    __shared__ uint32_t Bs[128 * GSTRIDE];

    const int tid  = threadIdx.x;
    const int lane = tid & 31;
    const int wid  = tid >> 5;
    const int g    = lane >> 2;
    const int t    = lane & 3;
    const int wm   = wid >> 2;
    const int wn   = wid & 3;

    const int rowBase = blockIdx.y * 128;
    const int colBase = blockIdx.x * 128;

    float4 aST[4], bST[4];
    const float* Ag = A + (size_t)rowBase * K;
    const float* Bg = B + (size_t)colBase * K;

    #pragma unroll
    for (int i = 0; i < 4; i++) {
        const int id = tid + i * 256;
        const int r  = id >> 3, c4 = (id & 7) * 4;
        aST[i] = *(const float4*)(Ag + (size_t)r * K + c4);
        bST[i] = *(const float4*)(Bg + (size_t)r * K + c4);
    }

    float acc[4][4][4];
    #pragma unroll
    for (int mi = 0; mi < 4; mi++)
        #pragma unroll
        for (int ni = 0; ni < 4; ni++)
            #pragma unroll
            for (int q = 0; q < 4; q++) acc[mi][ni][q] = 0.f;

    const int nIter = K / 32;
    for (int it = 0; it < nIter; it++) {
        #pragma unroll
        for (int i = 0; i < 4; i++) {
            const int id = tid + i * 256;
            const int r  = id >> 3, c4 = (id & 7) * 4;
            uint32_t* as = As + r * GSTRIDE + c4;
            uint32_t* bs = Bs + r * GSTRIDE + c4;
            as[0] = f2tf32(aST[i].x); as[1] = f2tf32(aST[i].y);
            as[2] = f2tf32(aST[i].z); as[3] = f2tf32(aST[i].w);
            bs[0] = f2tf32(bST[i].x); bs[1] = f2tf32(bST[i].y);
            bs[2] = f2tf32(bST[i].z); bs[3] = f2tf32(bST[i].w);
        }
        __syncthreads();

        if (it + 1 < nIter) {
            const int k0 = (it + 1) * 32;
            #pragma unroll
            for (int i = 0; i < 4; i++) {
                const int id = tid + i * 256;
                const int r  = id >> 3, c4 = (id & 7) * 4;
                aST[i] = *(const float4*)(Ag + (size_t)r * K + k0 + c4);
                bST[i] = *(const float4*)(Bg + (size_t)r * K + k0 + c4);
            }
        }

        #pragma unroll
        for (int kk = 0; kk < 32; kk += 8) {
            uint32_t af[4][4], bf[4][2];
            #pragma unroll
            for (int mi = 0; mi < 4; mi++) {
                const int rb = wm * 64 + mi * 16;
                af[mi][0] = As[(rb + g    ) * GSTRIDE + kk + t    ];
                af[mi][1] = As[(rb + g + 8) * GSTRIDE + kk + t    ];
                af[mi][2] = As[(rb + g    ) * GSTRIDE + kk + t + 4];
                af[mi][3] = As[(rb + g + 8) * GSTRIDE + kk + t + 4];
            }
            #pragma unroll
            for (int ni = 0; ni < 4; ni++) {
                const int nb = wn * 32 + ni * 8;
                bf[ni][0] = Bs[(nb + g) * GSTRIDE + kk + t    ];
                bf[ni][1] = Bs[(nb + g) * GSTRIDE + kk + t + 4];
            }
            #pragma unroll
            for (int mi = 0; mi < 4; mi++)
                #pragma unroll
                for (int ni = 0; ni < 4; ni++)
                    mma_tf32(acc[mi][ni],
                             af[mi][0], af[mi][1], af[mi][2], af[mi][3],
                             bf[ni][0], bf[ni][1]);
        }
        __syncthreads();
    }

    #pragma unroll
    for (int mi = 0; mi < 4; mi++) {
        const int r0 = rowBase + wm * 64 + mi * 16 + g;
        #pragma unroll
        for (int ni = 0; ni < 4; ni++) {
            const int cidx = colBase + wn * 32 + ni * 8 + 2 * t;
            float b0 = 0.f, b1 = 0.f;
            if (bias) { b0 = bias[cidx]; b1 = bias[cidx + 1]; }
            float2 v01 = make_float2(acc[mi][ni][0] + b0, acc[mi][ni][1] + b1);
            float2 v23 = make_float2(acc[mi][ni][2] + b0, acc[mi][ni][3] + b1);
            *(float2*)(C + (size_t)r0 * N + cidx)       = v01;
            *(float2*)(C + (size_t)(r0 + 8) * N + cidx) = v23;
        }
    }
}

// ---------------------------------------------------------------------------
// Tensor-core flash attention (tf32 MMA), 64x64 tiles.
// 256 threads = 8 warps in 4(row) x 2(col) layout; warp tile 16x32.
// Smem strides: Q/K/S = 68 (≡4 mod 32 -> frag addr 4g+t = lane, conflict-free)
//               V     = 72 (≡8 mod 32 -> frag addr 8t+g, conflict-free)
// ---------------------------------------------------------------------------
#define ALD 68
#define VLD 72

__global__ __launch_bounds__(256) void attn_tc_kernel(
    const float* __restrict__ Q, const float* __restrict__ K,
    const float* __restrict__ V, float* __restrict__ O)
{
    extern __shared__ uint32_t smu[];
    uint32_t* Qs = smu;                    // 64 x 68 (tf32, pre-scaled)
    uint32_t* Ks = Qs + 64 * ALD;          // 64 x 68 (tf32)
    uint32_t* Vs = Ks + 64 * ALD;          // 64 x 72 (tf32)
    uint32_t* Ss = Vs + 64 * VLD;          // 64 x 68 (S as float, then P as tf32)
    float* Sf   = (float*)Ss;
    float* mrow = (float*)(Ss + 64 * ALD); // 64
    float* lrow = mrow + 64;               // 64
    float* arow = lrow + 64;               // 64

    const int tid  = threadIdx.x;
    const int lane = tid & 31;
    const int wid  = tid >> 5;
    const int g    = lane >> 2;
    const int t    = lane & 3;
    const int rb   = (wid >> 1) * 16;      // warp row base (0,16,32,48)
    const int cbW  = (wid & 1) * 32;       // warp col base (0,32)

    const int bh = blockIdx.y;
    const int b  = bh / NHEAD;
    const int h  = bh % NHEAD;
    const int q0 = blockIdx.x * 64;

    const float* Qg = Q + (size_t)b * SEQ * DMODEL + h * DHEAD;
    const float* Kg = K + (size_t)b * SEQ * DMODEL + h * DHEAD;
    const float* Vg = V + (size_t)b * SEQ * DMODEL + h * DHEAD;

    // load Q tile (pre-scaled by 1/8 = 1/sqrt(64), exact)
    #pragma unroll
    for (int i = 0; i < 4; i++) {
        const int id = tid + i * 256;
        const int r = id >> 4, c4 = (id & 15) * 4;
        float4 v = *(const float4*)(Qg + (size_t)(q0 + r) * DMODEL + c4);
        uint32_t* q = Qs + r * ALD + c4;
        q[0] = f2tf32(v.x * 0.125f); q[1] = f2tf32(v.y * 0.125f);
        q[2] = f2tf32(v.z * 0.125f); q[3] = f2tf32(v.w * 0.125f);
    }
    if (tid < 64) { mrow[tid] = -1e30f; lrow[tid] = 0.f; }

    float acc[4][4];
    #pragma unroll
    for (int ni = 0; ni < 4; ni++)
        #pragma unroll
        for (int q = 0; q < 4; q++) acc[ni][q] = 0.f;

    for (int k0 = 0; k0 < SEQ; k0 += 64) {
        __syncthreads();   // protect smem reuse (K/V/S) against prior-iter reads
        #pragma unroll
        for (int i = 0; i < 4; i++) {
            const int id = tid + i * 256;
            const int r = id >> 4, c4 = (id & 15) * 4;
            float4 kv = *(const float4*)(Kg + (size_t)(k0 + r) * DMODEL + c4);
            float4 vv = *(const float4*)(Vg + (size_t)(k0 + r) * DMODEL + c4);
            uint32_t* ks = Ks + r * ALD + c4;
            ks[0] = f2tf32(kv.x); ks[1] = f2tf32(kv.y);
            ks[2] = f2tf32(kv.z); ks[3] = f2tf32(kv.w);
            uint32_t* vs = Vs + r * VLD + c4;
            vs[0] = f2tf32(vv.x); vs[1] = f2tf32(vv.y);
            vs[2] = f2tf32(vv.z); vs[3] = f2tf32(vv.w);
        }
        __syncthreads();

        // S = Qscaled @ K^T  (16x32 per warp)
        float s[4][4];
        #pragma unroll
        for (int ni = 0; ni < 4; ni++)
            #pragma unroll
            for (int q = 0; q < 4; q++) s[ni][q] = 0.f;
        #pragma unroll
        for (int kk = 0; kk < 64; kk += 8) {
            const uint32_t a0 = Qs[(rb + g    ) * ALD + kk + t    ];
            const uint32_t a1 = Qs[(rb + g + 8) * ALD + kk + t    ];
            const uint32_t a2 = Qs[(rb + g    ) * ALD + kk + t + 4];
            const uint32_t a3 = Qs[(rb + g + 8) * ALD + kk + t + 4];
            #pragma unroll
            for (int ni = 0; ni < 4; ni++) {
                const int nb = cbW + ni * 8;
                const uint32_t b0 = Ks[(nb + g) * ALD + kk + t    ];
                const uint32_t b1 = Ks[(nb + g) * ALD + kk + t + 4];
                mma_tf32(s[ni], a0, a1, a2, a3, b0, b1);
            }
        }
        // scatter S to smem (float)
        #pragma unroll
        for (int ni = 0; ni < 4; ni++) {
            const int c = cbW + ni * 8 + 2 * t;
            *(float2*)(Sf + (rb + g    ) * ALD + c) = make_float2(s[ni][0], s[ni][1]);
            *(float2*)(Sf + (rb + g + 8) * ALD + c) = make_float2(s[ni][2], s[ni][3]);
        }
        __syncthreads();

        // softmax: 4 threads per row, 16 cols each, quad shfl reduce
        {
            const int row = tid >> 2;
            const int qt  = tid & 3;
            float* srow = Sf + row * ALD + qt * 16;
            float mx = -1e30f;
            #pragma unroll
            for (int j = 0; j < 16; j++) mx = fmaxf(mx, srow[j]);
            mx = fmaxf(mx, __shfl_xor_sync(0xffffffffu, mx, 1));
            mx = fmaxf(mx, __shfl_xor_sync(0xffffffffu, mx, 2));
            const float mo = mrow[row];
            mx = fmaxf(mx, mo);
            float sum = 0.f;
            uint32_t* prow = Ss + row * ALD + qt * 16;
            #pragma unroll
            for (int j = 0; j < 16; j++) {
                const float p = __expf(srow[j] - mx);
                sum += p;
                prow[j] = f2tf32(p);
            }
            sum += __shfl_xor_sync(0xffffffffu, sum, 1);
            sum += __shfl_xor_sync(0xffffffffu, sum, 2);
            if (qt == 0) {
                const float a = __expf(mo - mx);
                arow[row] = a;
                mrow[row] = mx;
                lrow[row] = lrow[row] * a + sum;
            }
        }
        __syncthreads();

        // acc = acc*alpha + P @ V
        const float al0 = arow[rb + g];
        const float al1 = arow[rb + g + 8];
        #pragma unroll
        for (int ni = 0; ni < 4; ni++) {
            acc[ni][0] *= al0; acc[ni][1] *= al0;
            acc[ni][2] *= al1; acc[ni][3] *= al1;
        }
        #pragma unroll
        for (int kk = 0; kk < 64; kk += 8) {
            const uint32_t a0 = Ss[(rb + g    ) * ALD + kk + t    ];
            const uint32_t a1 = Ss[(rb + g + 8) * ALD + kk + t    ];
            const uint32_t a2 = Ss[(rb + g    ) * ALD + kk + t + 4];
            const uint32_t a3 = Ss[(rb + g + 8) * ALD + kk + t + 4];
            #pragma unroll
            for (int ni = 0; ni < 4; ni++) {
                const int nb = cbW + ni * 8;
                const uint32_t b0 = Vs[(kk + t    ) * VLD + nb + g];
                const uint32_t b1 = Vs[(kk + t + 4) * VLD + nb + g];
                mma_tf32(acc[ni], a0, a1, a2, a3, b0, b1);
            }
        }
    }

    // epilogue: normalize, store
    const float li0 = 1.f / lrow[rb + g];
    const float li1 = 1.f / lrow[rb + g + 8];
    float* Og = O + (size_t)b * SEQ * DMODEL + h * DHEAD;
    #pragma unroll
    for (int ni = 0; ni < 4; ni++) {
        const int c = cbW + ni * 8 + 2 * t;
        *(float2*)(Og + (size_t)(q0 + rb + g    ) * DMODEL + c) =
            make_float2(acc[ni][0] * li0, acc[ni][1] * li0);
        *(float2*)(Og + (size_t)(q0 + rb + g + 8) * DMODEL + c) =
            make_float2(acc[ni][2] * li1, acc[ni][3] * li1);
    }
}

// ---------------------------------------------------------------------------
// Launch
// ---------------------------------------------------------------------------
extern "C" void kernel_launch(void* const* d_in, const int* in_sizes, int n_in,
                              void* d_out, int out_size)
{
    const float* z   = (const float*)d_in[0];
    const float* w_q = (const float*)d_in[1];
    const float* w_k = (const float*)d_in[2];
    const float* w_v = (const float*)d_in[3];
    const float* w_o = (const float*)d_in[4];
    const float* b_o = (const float*)d_in[5];
    float* out = (float*)d_out;

    float *Qp, *Kp, *Vp, *AOp;
    cudaGetSymbolAddress((void**)&Qp,  g_Q);
    cudaGetSymbolAddress((void**)&Kp,  g_K);
    cudaGetSymbolAddress((void**)&Vp,  g_V);
    cudaGetSymbolAddress((void**)&AOp, g_AO);

    const dim3 gemmGrid(DMODEL / 128, MTOT / 128);

    gemm_tf32_kernel<<<gemmGrid, 256>>>(z, w_q, nullptr, Qp, MTOT, DMODEL, DMODEL);
    gemm_tf32_kernel<<<gemmGrid, 256>>>(z, w_k, nullptr, Kp, MTOT, DMODEL, DMODEL);
    gemm_tf32_kernel<<<gemmGrid, 256>>>(z, w_v, nullptr, Vp, MTOT, DMODEL, DMODEL);

    const int attnSmem = (3 * 64 * ALD + 64 * VLD + 192) * (int)sizeof(float);
    static bool attrSet = false;
    if (!attrSet) {
        cudaFuncSetAttribute(attn_tc_kernel,
                             cudaFuncAttributeMaxDynamicSharedMemorySize,
                             attnSmem);
        attrSet = true;
    }
    attn_tc_kernel<<<dim3(SEQ / 64, BATCH * NHEAD), 256, attnSmem>>>(Qp, Kp, Vp, AOp);

    gemm_tf32_kernel<<<gemmGrid, 256>>>(AOp, w_o, b_o, out, MTOT, DMODEL, DMODEL);
}

// round 7
// speedup vs baseline: 4.6307x; 1.2614x over previous
#include <cuda_runtime.h>
#include <cuda_fp16.h>
#include <math.h>
#include <stdint.h>

#define BATCH   8
#define SEQ     1024
#define DMODEL  768
#define NHEAD   12
#define DHEAD   64
#define MTOT    (BATCH * SEQ)   // 8192

__device__ float g_Q [MTOT * DMODEL];
__device__ float g_K [MTOT * DMODEL];
__device__ float g_V [MTOT * DMODEL];
__device__ float g_AO[MTOT * DMODEL];

// ---------------------------------------------------------------------------
// TF32 helpers (projection GEMMs — unchanged, known-good)
// ---------------------------------------------------------------------------
__device__ __forceinline__ uint32_t f2tf32(float x) {
    uint32_t y;
    asm("cvt.rna.tf32.f32 %0, %1;" : "=r"(y) : "f"(x));
    return y;
}

__device__ __forceinline__ void mma_tf32(float c[4],
    uint32_t a0, uint32_t a1, uint32_t a2, uint32_t a3,
    uint32_t b0, uint32_t b1)
{
    asm volatile(
        "mma.sync.aligned.m16n8k8.row.col.f32.tf32.tf32.f32 "
        "{%0,%1,%2,%3}, {%4,%5,%6,%7}, {%8,%9}, {%0,%1,%2,%3};"
        : "+f"(c[0]), "+f"(c[1]), "+f"(c[2]), "+f"(c[3])
        : "r"(a0), "r"(a1), "r"(a2), "r"(a3), "r"(b0), "r"(b1));
}

// fp16 MMA m16n8k16, f32 accumulate
__device__ __forceinline__ void mma_f16(float c[4],
    uint32_t a0, uint32_t a1, uint32_t a2, uint32_t a3,
    uint32_t b0, uint32_t b1)
{
    asm volatile(
        "mma.sync.aligned.m16n8k16.row.col.f32.f16.f16.f32 "
        "{%0,%1,%2,%3}, {%4,%5,%6,%7}, {%8,%9}, {%0,%1,%2,%3};"
        : "+f"(c[0]), "+f"(c[1]), "+f"(c[2]), "+f"(c[3])
        : "r"(a0), "r"(a1), "r"(a2), "r"(a3), "r"(b0), "r"(b1));
}

__device__ __forceinline__ uint32_t h2u(__half2 h) {
    return *reinterpret_cast<uint32_t*>(&h);
}

// ---------------------------------------------------------------------------
// TF32 tensor-core GEMM (NT): C[M,N] = A[M,K] @ B[N,K]^T (+ bias[N])
// ---------------------------------------------------------------------------
#define GSTRIDE 36

__global__ __launch_bounds__(256) void gemm_tf32_kernel(
    const float* __restrict__ A, const float* __restrict__ B,
    const float* __restrict__ bias, float* __restrict__ C,
    int M, int N, int K)
{
    __shared__ uint32_t As[128 * GSTRIDE];
    __shared__ uint32_t Bs[128 * GSTRIDE];

    const int tid  = threadIdx.x;
    const int lane = tid & 31;
    const int wid  = tid >> 5;
    const int g    = lane >> 2;
    const int t    = lane & 3;
    const int wm   = wid >> 2;
    const int wn   = wid & 3;

    const int rowBase = blockIdx.y * 128;
    const int colBase = blockIdx.x * 128;

    float4 aST[4], bST[4];
    const float* Ag = A + (size_t)rowBase * K;
    const float* Bg = B + (size_t)colBase * K;

    #pragma unroll
    for (int i = 0; i < 4; i++) {
        const int id = tid + i * 256;
        const int r  = id >> 3, c4 = (id & 7) * 4;
        aST[i] = *(const float4*)(Ag + (size_t)r * K + c4);
        bST[i] = *(const float4*)(Bg + (size_t)r * K + c4);
    }

    float acc[4][4][4];
    #pragma unroll
    for (int mi = 0; mi < 4; mi++)
        #pragma unroll
        for (int ni = 0; ni < 4; ni++)
            #pragma unroll
            for (int q = 0; q < 4; q++) acc[mi][ni][q] = 0.f;

    const int nIter = K / 32;
    for (int it = 0; it < nIter; it++) {
        #pragma unroll
        for (int i = 0; i < 4; i++) {
            const int id = tid + i * 256;
            const int r  = id >> 3, c4 = (id & 7) * 4;
            uint32_t* as = As + r * GSTRIDE + c4;
            uint32_t* bs = Bs + r * GSTRIDE + c4;
            as[0] = f2tf32(aST[i].x); as[1] = f2tf32(aST[i].y);
            as[2] = f2tf32(aST[i].z); as[3] = f2tf32(aST[i].w);
            bs[0] = f2tf32(bST[i].x); bs[1] = f2tf32(bST[i].y);
            bs[2] = f2tf32(bST[i].z); bs[3] = f2tf32(bST[i].w);
        }
        __syncthreads();

        if (it + 1 < nIter) {
            const int k0 = (it + 1) * 32;
            #pragma unroll
            for (int i = 0; i < 4; i++) {
                const int id = tid + i * 256;
                const int r  = id >> 3, c4 = (id & 7) * 4;
                aST[i] = *(const float4*)(Ag + (size_t)r * K + k0 + c4);
                bST[i] = *(const float4*)(Bg + (size_t)r * K + k0 + c4);
            }
        }

        #pragma unroll
        for (int kk = 0; kk < 32; kk += 8) {
            uint32_t af[4][4], bf[4][2];
            #pragma unroll
            for (int mi = 0; mi < 4; mi++) {
                const int rb = wm * 64 + mi * 16;
                af[mi][0] = As[(rb + g    ) * GSTRIDE + kk + t    ];
                af[mi][1] = As[(rb + g + 8) * GSTRIDE + kk + t    ];
                af[mi][2] = As[(rb + g    ) * GSTRIDE + kk + t + 4];
                af[mi][3] = As[(rb + g + 8) * GSTRIDE + kk + t + 4];
            }
            #pragma unroll
            for (int ni = 0; ni < 4; ni++) {
                const int nb = wn * 32 + ni * 8;
                bf[ni][0] = Bs[(nb + g) * GSTRIDE + kk + t    ];
                bf[ni][1] = Bs[(nb + g) * GSTRIDE + kk + t + 4];
            }
            #pragma unroll
            for (int mi = 0; mi < 4; mi++)
                #pragma unroll
                for (int ni = 0; ni < 4; ni++)
                    mma_tf32(acc[mi][ni],
                             af[mi][0], af[mi][1], af[mi][2], af[mi][3],
                             bf[ni][0], bf[ni][1]);
        }
        __syncthreads();
    }

    #pragma unroll
    for (int mi = 0; mi < 4; mi++) {
        const int r0 = rowBase + wm * 64 + mi * 16 + g;
        #pragma unroll
        for (int ni = 0; ni < 4; ni++) {
            const int cidx = colBase + wn * 32 + ni * 8 + 2 * t;
            float b0 = 0.f, b1 = 0.f;
            if (bias) { b0 = bias[cidx]; b1 = bias[cidx + 1]; }
            float2 v01 = make_float2(acc[mi][ni][0] + b0, acc[mi][ni][1] + b1);
            float2 v23 = make_float2(acc[mi][ni][2] + b0, acc[mi][ni][3] + b1);
            *(float2*)(C + (size_t)r0 * N + cidx)       = v01;
            *(float2*)(C + (size_t)(r0 + 8) * N + cidx) = v23;
        }
    }
}

// ---------------------------------------------------------------------------
// FA2-style fp16 tensor-core flash attention.
// BM=128 Q rows/CTA, BN=64 K/V chunk, 8 warps, warp tile 16 rows x 64 cols.
// S and P live in registers; softmax via quad shuffles; P->A-frag repack is
// pure register packing (C-layout cols {8nj+2t,2t+1} == A-frag half2 pairs).
// All smem strides 72 halfs (144B): frag LDS bank = 4g+t (conflict-free).
// Q pre-scaled by 0.125*log2(e); probabilities via exp2f.
// ---------------------------------------------------------------------------
#define ALD 72   // halfs

__global__ __launch_bounds__(256) void attn_fa2_kernel(
    const float* __restrict__ Q, const float* __restrict__ K,
    const float* __restrict__ V, float* __restrict__ O)
{
    __shared__ __half Qs[128 * ALD];
    __shared__ __half Ks[ 64 * ALD];
    __shared__ __half Vt[ 64 * ALD];   // [dh][seq]

    const int tid  = threadIdx.x;
    const int lane = tid & 31;
    const int wid  = tid >> 5;
    const int g    = lane >> 2;
    const int t    = lane & 3;
    const int rb   = wid * 16;

    const int bh = blockIdx.y;
    const int b  = bh / NHEAD;
    const int h  = bh % NHEAD;
    const int q0 = blockIdx.x * 128;

    const float* Qg = Q + (size_t)b * SEQ * DMODEL + h * DHEAD;
    const float* Kg = K + (size_t)b * SEQ * DMODEL + h * DHEAD;
    const float* Vg = V + (size_t)b * SEQ * DMODEL + h * DHEAD;

    const float QSCALE = 0.125f * 1.4426950408889634f;  // 1/sqrt(64) * log2(e)

    // load Q tile (128 x 64) as fp16, pre-scaled
    #pragma unroll
    for (int i = 0; i < 8; i++) {
        const int id = tid + i * 256;
        const int r = id >> 4, c4 = (id & 15) * 4;
        float4 v = *(const float4*)(Qg + (size_t)(q0 + r) * DMODEL + c4);
        uint2 pk;
        pk.x = h2u(__floats2half2_rn(v.x * QSCALE, v.y * QSCALE));
        pk.y = h2u(__floats2half2_rn(v.z * QSCALE, v.w * QSCALE));
        *(uint2*)(Qs + r * ALD + c4) = pk;
    }

    float o[8][4];
    #pragma unroll
    for (int nj = 0; nj < 8; nj++)
        #pragma unroll
        for (int q = 0; q < 4; q++) o[nj][q] = 0.f;
    float m0 = -1e30f, m1 = -1e30f, l0 = 0.f, l1 = 0.f;

    for (int k0 = 0; k0 < SEQ; k0 += 64) {
        __syncthreads();   // protect K/V smem reuse (also fences Q on iter 0)

        // K chunk (64 x 64) fp16
        #pragma unroll
        for (int i = 0; i < 4; i++) {
            const int id = tid + i * 256;
            const int r = id >> 4, c4 = (id & 15) * 4;
            float4 v = *(const float4*)(Kg + (size_t)(k0 + r) * DMODEL + c4);
            uint2 pk;
            pk.x = h2u(__floats2half2_rn(v.x, v.y));
            pk.y = h2u(__floats2half2_rn(v.z, v.w));
            *(uint2*)(Ks + r * ALD + c4) = pk;
        }
        // V chunk transposed: Vt[dh][seq], half2 pairs along seq
        #pragma unroll
        for (int i = 0; i < 2; i++) {
            const int id = tid + i * 256;   // 0..511
            const int d4 = id >> 5, p = id & 31;
            const float* v0p = Vg + (size_t)(k0 + 2 * p) * DMODEL + 4 * d4;
            float4 v0 = *(const float4*)(v0p);
            float4 v1 = *(const float4*)(v0p + DMODEL);
            *(uint32_t*)(Vt + (4 * d4 + 0) * ALD + 2 * p) = h2u(__floats2half2_rn(v0.x, v1.x));
            *(uint32_t*)(Vt + (4 * d4 + 1) * ALD + 2 * p) = h2u(__floats2half2_rn(v0.y, v1.y));
            *(uint32_t*)(Vt + (4 * d4 + 2) * ALD + 2 * p) = h2u(__floats2half2_rn(v0.z, v1.z));
            *(uint32_t*)(Vt + (4 * d4 + 3) * ALD + 2 * p) = h2u(__floats2half2_rn(v0.w, v1.w));
        }
        __syncthreads();

        // S = Qscaled @ K^T  (16 x 64 per warp, in registers; log2 domain)
        float s[8][4];
        #pragma unroll
        for (int nj = 0; nj < 8; nj++)
            #pragma unroll
            for (int q = 0; q < 4; q++) s[nj][q] = 0.f;
        #pragma unroll
        for (int kk = 0; kk < 4; kk++) {
            const uint32_t a0 = *(const uint32_t*)(Qs + (rb + g    ) * ALD + kk * 16 + 2 * t    );
            const uint32_t a1 = *(const uint32_t*)(Qs + (rb + g + 8) * ALD + kk * 16 + 2 * t    );
            const uint32_t a2 = *(const uint32_t*)(Qs + (rb + g    ) * ALD + kk * 16 + 2 * t + 8);
            const uint32_t a3 = *(const uint32_t*)(Qs + (rb + g + 8) * ALD + kk * 16 + 2 * t + 8);
            #pragma unroll
            for (int nj = 0; nj < 8; nj++) {
                const uint32_t b0 = *(const uint32_t*)(Ks + (nj * 8 + g) * ALD + kk * 16 + 2 * t    );
                const uint32_t b1 = *(const uint32_t*)(Ks + (nj * 8 + g) * ALD + kk * 16 + 2 * t + 8);
                mma_f16(s[nj], a0, a1, a2, a3, b0, b1);
            }
        }

        // online softmax in registers (rows g and g+8; quad = lanes 4g+t)
        float tm0 = -1e30f, tm1 = -1e30f;
        #pragma unroll
        for (int nj = 0; nj < 8; nj++) {
            tm0 = fmaxf(tm0, fmaxf(s[nj][0], s[nj][1]));
            tm1 = fmaxf(tm1, fmaxf(s[nj][2], s[nj][3]));
        }
        tm0 = fmaxf(tm0, __shfl_xor_sync(0xffffffffu, tm0, 1));
        tm0 = fmaxf(tm0, __shfl_xor_sync(0xffffffffu, tm0, 2));
        tm1 = fmaxf(tm1, __shfl_xor_sync(0xffffffffu, tm1, 1));
        tm1 = fmaxf(tm1, __shfl_xor_sync(0xffffffffu, tm1, 2));
        const float m0n = fmaxf(m0, tm0);
        const float m1n = fmaxf(m1, tm1);
        const float sc0 = exp2f(m0 - m0n);
        const float sc1 = exp2f(m1 - m1n);
        float sum0 = 0.f, sum1 = 0.f;
        #pragma unroll
        for (int nj = 0; nj < 8; nj++) {
            s[nj][0] = exp2f(s[nj][0] - m0n); sum0 += s[nj][0];
            s[nj][1] = exp2f(s[nj][1] - m0n); sum0 += s[nj][1];
            s[nj][2] = exp2f(s[nj][2] - m1n); sum1 += s[nj][2];
            s[nj][3] = exp2f(s[nj][3] - m1n); sum1 += s[nj][3];
        }
        sum0 += __shfl_xor_sync(0xffffffffu, sum0, 1);
        sum0 += __shfl_xor_sync(0xffffffffu, sum0, 2);
        sum1 += __shfl_xor_sync(0xffffffffu, sum1, 1);
        sum1 += __shfl_xor_sync(0xffffffffu, sum1, 2);
        l0 = l0 * sc0 + sum0;  m0 = m0n;
        l1 = l1 * sc1 + sum1;  m1 = m1n;
        #pragma unroll
        for (int nj = 0; nj < 8; nj++) {
            o[nj][0] *= sc0; o[nj][1] *= sc0;
            o[nj][2] *= sc1; o[nj][3] *= sc1;
        }

        // O += P @ V  (P packed from S registers; C-layout == A-frag layout)
        #pragma unroll
        for (int kc = 0; kc < 4; kc++) {
            const uint32_t a0 = h2u(__floats2half2_rn(s[2 * kc    ][0], s[2 * kc    ][1]));
            const uint32_t a1 = h2u(__floats2half2_rn(s[2 * kc    ][2], s[2 * kc    ][3]));
            const uint32_t a2 = h2u(__floats2half2_rn(s[2 * kc + 1][0], s[2 * kc + 1][1]));
            const uint32_t a3 = h2u(__floats2half2_rn(s[2 * kc + 1][2], s[2 * kc + 1][3]));
            #pragma unroll
            for (int nj = 0; nj < 8; nj++) {
                const uint32_t b0 = *(const uint32_t*)(Vt + (nj * 8 + g) * ALD + kc * 16 + 2 * t    );
                const uint32_t b1 = *(const uint32_t*)(Vt + (nj * 8 + g) * ALD + kc * 16 + 2 * t + 8);
                mma_f16(o[nj], a0, a1, a2, a3, b0, b1);
            }
        }
    }

    // epilogue
    const float li0 = 1.f / l0;
    const float li1 = 1.f / l1;
    float* Og = O + (size_t)b * SEQ * DMODEL + h * DHEAD;
    #pragma unroll
    for (int nj = 0; nj < 8; nj++) {
        const int c = nj * 8 + 2 * t;
        *(float2*)(Og + (size_t)(q0 + rb + g    ) * DMODEL + c) =
            make_float2(o[nj][0] * li0, o[nj][1] * li0);
        *(float2*)(Og + (size_t)(q0 + rb + g + 8) * DMODEL + c) =
            make_float2(o[nj][2] * li1, o[nj][3] * li1);
    }
}

// ---------------------------------------------------------------------------
// Launch
// ---------------------------------------------------------------------------
extern "C" void kernel_launch(void* const* d_in, const int* in_sizes, int n_in,
                              void* d_out, int out_size)
{
    const float* z   = (const float*)d_in[0];
    const float* w_q = (const float*)d_in[1];
    const float* w_k = (const float*)d_in[2];
    const float* w_v = (const float*)d_in[3];
    const float* w_o = (const float*)d_in[4];
    const float* b_o = (const float*)d_in[5];
    float* out = (float*)d_out;

    float *Qp, *Kp, *Vp, *AOp;
    cudaGetSymbolAddress((void**)&Qp,  g_Q);
    cudaGetSymbolAddress((void**)&Kp,  g_K);
    cudaGetSymbolAddress((void**)&Vp,  g_V);
    cudaGetSymbolAddress((void**)&AOp, g_AO);

    const dim3 gemmGrid(DMODEL / 128, MTOT / 128);

    gemm_tf32_kernel<<<gemmGrid, 256>>>(z, w_q, nullptr, Qp, MTOT, DMODEL, DMODEL);
    gemm_tf32_kernel<<<gemmGrid, 256>>>(z, w_k, nullptr, Kp, MTOT, DMODEL, DMODEL);
    gemm_tf32_kernel<<<gemmGrid, 256>>>(z, w_v, nullptr, Vp, MTOT, DMODEL, DMODEL);

    attn_fa2_kernel<<<dim3(SEQ / 128, BATCH * NHEAD), 256>>>(Qp, Kp, Vp, AOp);

    gemm_tf32_kernel<<<gemmGrid, 256>>>(AOp, w_o, b_o, out, MTOT, DMODEL, DMODEL);
}

// round 8
// speedup vs baseline: 5.7543x; 1.2427x over previous
#include <cuda_runtime.h>
#include <cuda_fp16.h>
#include <math.h>
#include <stdint.h>

#define BATCH   8
#define SEQ     1024
#define DMODEL  768
#define NHEAD   12
#define DHEAD   64
#define MTOT    (BATCH * SEQ)   // 8192

__device__ float g_Q [MTOT * DMODEL];
__device__ float g_K [MTOT * DMODEL];
__device__ float g_V [MTOT * DMODEL];
__device__ float g_AO[MTOT * DMODEL];

// ---------------------------------------------------------------------------
// MMA helpers
// ---------------------------------------------------------------------------
__device__ __forceinline__ void mma_f16(float c[4],
    uint32_t a0, uint32_t a1, uint32_t a2, uint32_t a3,
    uint32_t b0, uint32_t b1)
{
    asm volatile(
        "mma.sync.aligned.m16n8k16.row.col.f32.f16.f16.f32 "
        "{%0,%1,%2,%3}, {%4,%5,%6,%7}, {%8,%9}, {%0,%1,%2,%3};"
        : "+f"(c[0]), "+f"(c[1]), "+f"(c[2]), "+f"(c[3])
        : "r"(a0), "r"(a1), "r"(a2), "r"(a3), "r"(b0), "r"(b1));
}

__device__ __forceinline__ uint32_t h2u(__half2 h) {
    return *reinterpret_cast<uint32_t*>(&h);
}

// ---------------------------------------------------------------------------
// FP16 tensor-core GEMM (NT): C[M,N] = A[M,K] @ B[N,K]^T (+ bias[N])
// 128x128 block tile, BK=32, 256 threads (8 warps), warp tile 64x32.
// fp16 operands (converted at smem store), fp32 accumulate.
// Smem stride 40 halfs (20 words ≡ 20 mod 32 -> frag LDS conflict-free).
// ---------------------------------------------------------------------------
#define HSTRIDE 40   // halfs

__global__ __launch_bounds__(256) void gemm_f16_kernel(
    const float* __restrict__ A, const float* __restrict__ B,
    const float* __restrict__ bias, float* __restrict__ C,
    int M, int N, int K)
{
    __shared__ __half As[128 * HSTRIDE];
    __shared__ __half Bs[128 * HSTRIDE];

    const int tid  = threadIdx.x;
    const int lane = tid & 31;
    const int wid  = tid >> 5;
    const int g    = lane >> 2;
    const int t    = lane & 3;
    const int wm   = wid >> 2;
    const int wn   = wid & 3;

    const int rowBase = blockIdx.y * 128;
    const int colBase = blockIdx.x * 128;

    float4 aST[4], bST[4];
    const float* Ag = A + (size_t)rowBase * K;
    const float* Bg = B + (size_t)colBase * K;

    #pragma unroll
    for (int i = 0; i < 4; i++) {
        const int id = tid + i * 256;
        const int r  = id >> 3, c4 = (id & 7) * 4;
        aST[i] = *(const float4*)(Ag + (size_t)r * K + c4);
        bST[i] = *(const float4*)(Bg + (size_t)r * K + c4);
    }

    float acc[4][4][4];
    #pragma unroll
    for (int mi = 0; mi < 4; mi++)
        #pragma unroll
        for (int ni = 0; ni < 4; ni++)
            #pragma unroll
            for (int q = 0; q < 4; q++) acc[mi][ni][q] = 0.f;

    const int nIter = K / 32;
    for (int it = 0; it < nIter; it++) {
        // commit staged regs -> smem (fp16 conversion)
        #pragma unroll
        for (int i = 0; i < 4; i++) {
            const int id = tid + i * 256;
            const int r  = id >> 3, c4 = (id & 7) * 4;
            uint2 pa, pb;
            pa.x = h2u(__floats2half2_rn(aST[i].x, aST[i].y));
            pa.y = h2u(__floats2half2_rn(aST[i].z, aST[i].w));
            pb.x = h2u(__floats2half2_rn(bST[i].x, bST[i].y));
            pb.y = h2u(__floats2half2_rn(bST[i].z, bST[i].w));
            *(uint2*)(As + r * HSTRIDE + c4) = pa;
            *(uint2*)(Bs + r * HSTRIDE + c4) = pb;
        }
        __syncthreads();

        // prefetch next tile
        if (it + 1 < nIter) {
            const int k0 = (it + 1) * 32;
            #pragma unroll
            for (int i = 0; i < 4; i++) {
                const int id = tid + i * 256;
                const int r  = id >> 3, c4 = (id & 7) * 4;
                aST[i] = *(const float4*)(Ag + (size_t)r * K + k0 + c4);
                bST[i] = *(const float4*)(Bg + (size_t)r * K + k0 + c4);
            }
        }

        // compute: 2 k-steps of 16
        #pragma unroll
        for (int kk = 0; kk < 2; kk++) {
            uint32_t af[4][4], bf[4][2];
            #pragma unroll
            for (int mi = 0; mi < 4; mi++) {
                const int rb = wm * 64 + mi * 16;
                af[mi][0] = *(const uint32_t*)(As + (rb + g    ) * HSTRIDE + kk * 16 + 2 * t    );
                af[mi][1] = *(const uint32_t*)(As + (rb + g + 8) * HSTRIDE + kk * 16 + 2 * t    );
                af[mi][2] = *(const uint32_t*)(As + (rb + g    ) * HSTRIDE + kk * 16 + 2 * t + 8);
                af[mi][3] = *(const uint32_t*)(As + (rb + g + 8) * HSTRIDE + kk * 16 + 2 * t + 8);
            }
            #pragma unroll
            for (int ni = 0; ni < 4; ni++) {
                const int nb = wn * 32 + ni * 8;
                bf[ni][0] = *(const uint32_t*)(Bs + (nb + g) * HSTRIDE + kk * 16 + 2 * t    );
                bf[ni][1] = *(const uint32_t*)(Bs + (nb + g) * HSTRIDE + kk * 16 + 2 * t + 8);
            }
            #pragma unroll
            for (int mi = 0; mi < 4; mi++)
                #pragma unroll
                for (int ni = 0; ni < 4; ni++)
                    mma_f16(acc[mi][ni],
                            af[mi][0], af[mi][1], af[mi][2], af[mi][3],
                            bf[ni][0], bf[ni][1]);
        }
        __syncthreads();
    }

    #pragma unroll
    for (int mi = 0; mi < 4; mi++) {
        const int r0 = rowBase + wm * 64 + mi * 16 + g;
        #pragma unroll
        for (int ni = 0; ni < 4; ni++) {
            const int cidx = colBase + wn * 32 + ni * 8 + 2 * t;
            float b0 = 0.f, b1 = 0.f;
            if (bias) { b0 = bias[cidx]; b1 = bias[cidx + 1]; }
            float2 v01 = make_float2(acc[mi][ni][0] + b0, acc[mi][ni][1] + b1);
            float2 v23 = make_float2(acc[mi][ni][2] + b0, acc[mi][ni][3] + b1);
            *(float2*)(C + (size_t)r0 * N + cidx)       = v01;
            *(float2*)(C + (size_t)(r0 + 8) * N + cidx) = v23;
        }
    }
}

// ---------------------------------------------------------------------------
// FA2-style fp16 tensor-core flash attention (unchanged from R7).
// ---------------------------------------------------------------------------
#define ALD 72   // halfs

__global__ __launch_bounds__(256) void attn_fa2_kernel(
    const float* __restrict__ Q, const float* __restrict__ K,
    const float* __restrict__ V, float* __restrict__ O)
{
    __shared__ __half Qs[128 * ALD];
    __shared__ __half Ks[ 64 * ALD];
    __shared__ __half Vt[ 64 * ALD];   // [dh][seq]

    const int tid  = threadIdx.x;
    const int lane = tid & 31;
    const int wid  = tid >> 5;
    const int g    = lane >> 2;
    const int t    = lane & 3;
    const int rb   = wid * 16;

    const int bh = blockIdx.y;
    const int b  = bh / NHEAD;
    const int h  = bh % NHEAD;
    const int q0 = blockIdx.x * 128;

    const float* Qg = Q + (size_t)b * SEQ * DMODEL + h * DHEAD;
    const float* Kg = K + (size_t)b * SEQ * DMODEL + h * DHEAD;
    const float* Vg = V + (size_t)b * SEQ * DMODEL + h * DHEAD;

    const float QSCALE = 0.125f * 1.4426950408889634f;

    #pragma unroll
    for (int i = 0; i < 8; i++) {
        const int id = tid + i * 256;
        const int r = id >> 4, c4 = (id & 15) * 4;
        float4 v = *(const float4*)(Qg + (size_t)(q0 + r) * DMODEL + c4);
        uint2 pk;
        pk.x = h2u(__floats2half2_rn(v.x * QSCALE, v.y * QSCALE));
        pk.y = h2u(__floats2half2_rn(v.z * QSCALE, v.w * QSCALE));
        *(uint2*)(Qs + r * ALD + c4) = pk;
    }

    float o[8][4];
    #pragma unroll
    for (int nj = 0; nj < 8; nj++)
        #pragma unroll
        for (int q = 0; q < 4; q++) o[nj][q] = 0.f;
    float m0 = -1e30f, m1 = -1e30f, l0 = 0.f, l1 = 0.f;

    for (int k0 = 0; k0 < SEQ; k0 += 64) {
        __syncthreads();

        #pragma unroll
        for (int i = 0; i < 4; i++) {
            const int id = tid + i * 256;
            const int r = id >> 4, c4 = (id & 15) * 4;
            float4 v = *(const float4*)(Kg + (size_t)(k0 + r) * DMODEL + c4);
            uint2 pk;
            pk.x = h2u(__floats2half2_rn(v.x, v.y));
            pk.y = h2u(__floats2half2_rn(v.z, v.w));
            *(uint2*)(Ks + r * ALD + c4) = pk;
        }
        #pragma unroll
        for (int i = 0; i < 2; i++) {
            const int id = tid + i * 256;
            const int d4 = id >> 5, p = id & 31;
            const float* v0p = Vg + (size_t)(k0 + 2 * p) * DMODEL + 4 * d4;
            float4 v0 = *(const float4*)(v0p);
            float4 v1 = *(const float4*)(v0p + DMODEL);
            *(uint32_t*)(Vt + (4 * d4 + 0) * ALD + 2 * p) = h2u(__floats2half2_rn(v0.x, v1.x));
            *(uint32_t*)(Vt + (4 * d4 + 1) * ALD + 2 * p) = h2u(__floats2half2_rn(v0.y, v1.y));
            *(uint32_t*)(Vt + (4 * d4 + 2) * ALD + 2 * p) = h2u(__floats2half2_rn(v0.z, v1.z));
            *(uint32_t*)(Vt + (4 * d4 + 3) * ALD + 2 * p) = h2u(__floats2half2_rn(v0.w, v1.w));
        }
        __syncthreads();

        float s[8][4];
        #pragma unroll
        for (int nj = 0; nj < 8; nj++)
            #pragma unroll
            for (int q = 0; q < 4; q++) s[nj][q] = 0.f;
        #pragma unroll
        for (int kk = 0; kk < 4; kk++) {
            const uint32_t a0 = *(const uint32_t*)(Qs + (rb + g    ) * ALD + kk * 16 + 2 * t    );
            const uint32_t a1 = *(const uint32_t*)(Qs + (rb + g + 8) * ALD + kk * 16 + 2 * t    );
            const uint32_t a2 = *(const uint32_t*)(Qs + (rb + g    ) * ALD + kk * 16 + 2 * t + 8);
            const uint32_t a3 = *(const uint32_t*)(Qs + (rb + g + 8) * ALD + kk * 16 + 2 * t + 8);
            #pragma unroll
            for (int nj = 0; nj < 8; nj++) {
                const uint32_t b0 = *(const uint32_t*)(Ks + (nj * 8 + g) * ALD + kk * 16 + 2 * t    );
                const uint32_t b1 = *(const uint32_t*)(Ks + (nj * 8 + g) * ALD + kk * 16 + 2 * t + 8);
                mma_f16(s[nj], a0, a1, a2, a3, b0, b1);
            }
        }

        float tm0 = -1e30f, tm1 = -1e30f;
        #pragma unroll
        for (int nj = 0; nj < 8; nj++) {
            tm0 = fmaxf(tm0, fmaxf(s[nj][0], s[nj][1]));
            tm1 = fmaxf(tm1, fmaxf(s[nj][2], s[nj][3]));
        }
        tm0 = fmaxf(tm0, __shfl_xor_sync(0xffffffffu, tm0, 1));
        tm0 = fmaxf(tm0, __shfl_xor_sync(0xffffffffu, tm0, 2));
        tm1 = fmaxf(tm1, __shfl_xor_sync(0xffffffffu, tm1, 1));
        tm1 = fmaxf(tm1, __shfl_xor_sync(0xffffffffu, tm1, 2));
        const float m0n = fmaxf(m0, tm0);
        const float m1n = fmaxf(m1, tm1);
        const float sc0 = exp2f(m0 - m0n);
        const float sc1 = exp2f(m1 - m1n);
        float sum0 = 0.f, sum1 = 0.f;
        #pragma unroll
        for (int nj = 0; nj < 8; nj++) {
            s[nj][0] = exp2f(s[nj][0] - m0n); sum0 += s[nj][0];
            s[nj][1] = exp2f(s[nj][1] - m0n); sum0 += s[nj][1];
            s[nj][2] = exp2f(s[nj][2] - m1n); sum1 += s[nj][2];
            s[nj][3] = exp2f(s[nj][3] - m1n); sum1 += s[nj][3];
        }
        sum0 += __shfl_xor_sync(0xffffffffu, sum0, 1);
        sum0 += __shfl_xor_sync(0xffffffffu, sum0, 2);
        sum1 += __shfl_xor_sync(0xffffffffu, sum1, 1);
        sum1 += __shfl_xor_sync(0xffffffffu, sum1, 2);
        l0 = l0 * sc0 + sum0;  m0 = m0n;
        l1 = l1 * sc1 + sum1;  m1 = m1n;
        #pragma unroll
        for (int nj = 0; nj < 8; nj++) {
            o[nj][0] *= sc0; o[nj][1] *= sc0;
            o[nj][2] *= sc1; o[nj][3] *= sc1;
        }

        #pragma unroll
        for (int kc = 0; kc < 4; kc++) {
            const uint32_t a0 = h2u(__floats2half2_rn(s[2 * kc    ][0], s[2 * kc    ][1]));
            const uint32_t a1 = h2u(__floats2half2_rn(s[2 * kc    ][2], s[2 * kc    ][3]));
            const uint32_t a2 = h2u(__floats2half2_rn(s[2 * kc + 1][0], s[2 * kc + 1][1]));
            const uint32_t a3 = h2u(__floats2half2_rn(s[2 * kc + 1][2], s[2 * kc + 1][3]));
            #pragma unroll
            for (int nj = 0; nj < 8; nj++) {
                const uint32_t b0 = *(const uint32_t*)(Vt + (nj * 8 + g) * ALD + kc * 16 + 2 * t    );
                const uint32_t b1 = *(const uint32_t*)(Vt + (nj * 8 + g) * ALD + kc * 16 + 2 * t + 8);
                mma_f16(o[nj], a0, a1, a2, a3, b0, b1);
            }
        }
    }

    const float li0 = 1.f / l0;
    const float li1 = 1.f / l1;
    float* Og = O + (size_t)b * SEQ * DMODEL + h * DHEAD;
    #pragma unroll
    for (int nj = 0; nj < 8; nj++) {
        const int c = nj * 8 + 2 * t;
        *(float2*)(Og + (size_t)(q0 + rb + g    ) * DMODEL + c) =
            make_float2(o[nj][0] * li0, o[nj][1] * li0);
        *(float2*)(Og + (size_t)(q0 + rb + g + 8) * DMODEL + c) =
            make_float2(o[nj][2] * li1, o[nj][3] * li1);
    }
}

// ---------------------------------------------------------------------------
// Launch
// ---------------------------------------------------------------------------
extern "C" void kernel_launch(void* const* d_in, const int* in_sizes, int n_in,
                              void* d_out, int out_size)
{
    const float* z   = (const float*)d_in[0];
    const float* w_q = (const float*)d_in[1];
    const float* w_k = (const float*)d_in[2];
    const float* w_v = (const float*)d_in[3];
    const float* w_o = (const float*)d_in[4];
    const float* b_o = (const float*)d_in[5];
    float* out = (float*)d_out;

    float *Qp, *Kp, *Vp, *AOp;
    cudaGetSymbolAddress((void**)&Qp,  g_Q);
    cudaGetSymbolAddress((void**)&Kp,  g_K);
    cudaGetSymbolAddress((void**)&Vp,  g_V);
    cudaGetSymbolAddress((void**)&AOp, g_AO);

    const dim3 gemmGrid(DMODEL / 128, MTOT / 128);

    gemm_f16_kernel<<<gemmGrid, 256>>>(z, w_q, nullptr, Qp, MTOT, DMODEL, DMODEL);
    gemm_f16_kernel<<<gemmGrid, 256>>>(z, w_k, nullptr, Kp, MTOT, DMODEL, DMODEL);
    gemm_f16_kernel<<<gemmGrid, 256>>>(z, w_v, nullptr, Vp, MTOT, DMODEL, DMODEL);

    attn_fa2_kernel<<<dim3(SEQ / 128, BATCH * NHEAD), 256>>>(Qp, Kp, Vp, AOp);

    gemm_f16_kernel<<<gemmGrid, 256>>>(AOp, w_o, b_o, out, MTOT, DMODEL, DMODEL);
}

// round 9
// speedup vs baseline: 7.1241x; 1.2380x over previous
#include <cuda_runtime.h>
#include <cuda_fp16.h>
#include <math.h>
#include <stdint.h>

#define BATCH   8
#define SEQ     1024
#define DMODEL  768
#define NHEAD   12
#define DHEAD   64
#define MTOT    (BATCH * SEQ)   // 8192

// fp16 scratch
__device__ __half g_zh [MTOT * DMODEL];
__device__ __half g_wqh[DMODEL * DMODEL];
__device__ __half g_wkh[DMODEL * DMODEL];
__device__ __half g_wvh[DMODEL * DMODEL];
__device__ __half g_Qh [MTOT * DMODEL];
__device__ __half g_Kh [MTOT * DMODEL];
__device__ __half g_Vh [MTOT * DMODEL];
__device__ float  g_AO [MTOT * DMODEL];

// ---------------------------------------------------------------------------
// Helpers
// ---------------------------------------------------------------------------
__device__ __forceinline__ void mma_f16(float c[4],
    uint32_t a0, uint32_t a1, uint32_t a2, uint32_t a3,
    uint32_t b0, uint32_t b1)
{
    asm volatile(
        "mma.sync.aligned.m16n8k16.row.col.f32.f16.f16.f32 "
        "{%0,%1,%2,%3}, {%4,%5,%6,%7}, {%8,%9}, {%0,%1,%2,%3};"
        : "+f"(c[0]), "+f"(c[1]), "+f"(c[2]), "+f"(c[3])
        : "r"(a0), "r"(a1), "r"(a2), "r"(a3), "r"(b0), "r"(b1));
}

__device__ __forceinline__ uint32_t h2u(__half2 h) {
    return *reinterpret_cast<uint32_t*>(&h);
}

__device__ __forceinline__ void cp_async16(void* smem_dst, const void* gmem_src) {
    uint32_t s = (uint32_t)__cvta_generic_to_shared(smem_dst);
    asm volatile("cp.async.cg.shared.global [%0], [%1], 16;\n"
                 :: "r"(s), "l"(gmem_src));
}

// ---------------------------------------------------------------------------
// fp32 -> fp16 conversion (z + 3 weights in one launch)
// ---------------------------------------------------------------------------
#define NZ4 ((MTOT * DMODEL) / 4)        // 1572864
#define NW4 ((DMODEL * DMODEL) / 4)      // 147456

__global__ __launch_bounds__(256) void cvt_all_kernel(
    const float* __restrict__ z,  const float* __restrict__ wq,
    const float* __restrict__ wk, const float* __restrict__ wv)
{
    const int i = blockIdx.x * 256 + threadIdx.x;
    const float* src; __half* dst; int idx;
    if (i < NZ4)                { src = z;  dst = g_zh;  idx = i; }
    else if (i < NZ4 + NW4)     { src = wq; dst = g_wqh; idx = i - NZ4; }
    else if (i < NZ4 + 2*NW4)   { src = wk; dst = g_wkh; idx = i - NZ4 - NW4; }
    else if (i < NZ4 + 3*NW4)   { src = wv; dst = g_wvh; idx = i - NZ4 - 2*NW4; }
    else return;
    float4 v = ((const float4*)src)[idx];
    uint2 p;
    p.x = h2u(__floats2half2_rn(v.x, v.y));
    p.y = h2u(__floats2half2_rn(v.z, v.w));
    ((uint2*)dst)[idx] = p;
}

// ---------------------------------------------------------------------------
// Fused QKV GEMM (NT, fp16 in / fp16 out): 3-stage cp.async pipeline.
// grid = (N/128, M/128, 3). blockIdx.z picks (B, C, outScale).
// 128x128 tile, BK=32, 256 threads, warp tile 64x32, HSTRIDE=40 halfs.
// ---------------------------------------------------------------------------
#define HST   40
#define PSTG  3
#define STGH  (128 * HST)          // halfs per (A or B) stage

__global__ __launch_bounds__(256) void gemm_qkv_kernel(
    const __half* __restrict__ A, int M, int N, int K, float qscale)
{
    extern __shared__ __half sh[];
    __half* As = sh;                   // PSTG * STGH
    __half* Bs = sh + PSTG * STGH;

    const __half* B; __half* C; float outScale;
    if      (blockIdx.z == 0) { B = g_wqh; C = g_Qh; outScale = qscale; }
    else if (blockIdx.z == 1) { B = g_wkh; C = g_Kh; outScale = 1.f; }
    else                      { B = g_wvh; C = g_Vh; outScale = 1.f; }

    const int tid  = threadIdx.x;
    const int lane = tid & 31;
    const int wid  = tid >> 5;
    const int g    = lane >> 2;
    const int t    = lane & 3;
    const int wm   = wid >> 2;
    const int wn   = wid & 3;

    const int rowBase = blockIdx.y * 128;
    const int colBase = blockIdx.x * 128;
    const __half* Ag = A + (size_t)rowBase * K;
    const __half* Bg = B + (size_t)colBase * K;

    // issue one stage: A,B tiles are 128 rows x 4 chunks of 16B each
    auto issue = [&](int st) {
        const int buf = st % PSTG;
        const int k0  = st * 32;
        #pragma unroll
        for (int i = 0; i < 2; i++) {
            const int ch = tid + i * 256;         // 0..511
            const int r = ch >> 2, c = ch & 3;    // c*8 halfs = c*16B
            cp_async16(As + buf * STGH + r * HST + c * 8,
                       Ag + (size_t)r * K + k0 + c * 8);
            cp_async16(Bs + buf * STGH + r * HST + c * 8,
                       Bg + (size_t)r * K + k0 + c * 8);
        }
    };

    float acc[4][4][4];
    #pragma unroll
    for (int mi = 0; mi < 4; mi++)
        #pragma unroll
        for (int ni = 0; ni < 4; ni++)
            #pragma unroll
            for (int q = 0; q < 4; q++) acc[mi][ni][q] = 0.f;

    issue(0); asm volatile("cp.async.commit_group;" ::: "memory");
    issue(1); asm volatile("cp.async.commit_group;" ::: "memory");

    const int kIter = K / 32;   // 24
    for (int it = 0; it < kIter; it++) {
        asm volatile("cp.async.wait_group 1;" ::: "memory");
        __syncthreads();

        if (it + 2 < kIter) issue(it + 2);
        asm volatile("cp.async.commit_group;" ::: "memory");

        const __half* Ab = As + (it % PSTG) * STGH;
        const __half* Bb = Bs + (it % PSTG) * STGH;

        #pragma unroll
        for (int kk = 0; kk < 2; kk++) {
            uint32_t af[4][4], bf[4][2];
            #pragma unroll
            for (int mi = 0; mi < 4; mi++) {
                const int rb = wm * 64 + mi * 16;
                af[mi][0] = *(const uint32_t*)(Ab + (rb + g    ) * HST + kk * 16 + 2 * t    );
                af[mi][1] = *(const uint32_t*)(Ab + (rb + g + 8) * HST + kk * 16 + 2 * t    );
                af[mi][2] = *(const uint32_t*)(Ab + (rb + g    ) * HST + kk * 16 + 2 * t + 8);
                af[mi][3] = *(const uint32_t*)(Ab + (rb + g + 8) * HST + kk * 16 + 2 * t + 8);
            }
            #pragma unroll
            for (int ni = 0; ni < 4; ni++) {
                const int nb = wn * 32 + ni * 8;
                bf[ni][0] = *(const uint32_t*)(Bb + (nb + g) * HST + kk * 16 + 2 * t    );
                bf[ni][1] = *(const uint32_t*)(Bb + (nb + g) * HST + kk * 16 + 2 * t + 8);
            }
            #pragma unroll
            for (int mi = 0; mi < 4; mi++)
                #pragma unroll
                for (int ni = 0; ni < 4; ni++)
                    mma_f16(acc[mi][ni],
                            af[mi][0], af[mi][1], af[mi][2], af[mi][3],
                            bf[ni][0], bf[ni][1]);
        }
        __syncthreads();
    }

    // epilogue: fp16 store (scaled)
    #pragma unroll
    for (int mi = 0; mi < 4; mi++) {
        const int r0 = rowBase + wm * 64 + mi * 16 + g;
        #pragma unroll
        for (int ni = 0; ni < 4; ni++) {
            const int cidx = colBase + wn * 32 + ni * 8 + 2 * t;
            *(uint32_t*)(C + (size_t)r0 * N + cidx) =
                h2u(__floats2half2_rn(acc[mi][ni][0] * outScale, acc[mi][ni][1] * outScale));
            *(uint32_t*)(C + (size_t)(r0 + 8) * N + cidx) =
                h2u(__floats2half2_rn(acc[mi][ni][2] * outScale, acc[mi][ni][3] * outScale));
        }
    }
}

// ---------------------------------------------------------------------------
// FP16 GEMM for the O projection (fp32 A via register staging — unchanged R8)
// ---------------------------------------------------------------------------
__global__ __launch_bounds__(256) void gemm_f16_kernel(
    const float* __restrict__ A, const float* __restrict__ B,
    const float* __restrict__ bias, float* __restrict__ C,
    int M, int N, int K)
{
    __shared__ __half As[128 * HST];
    __shared__ __half Bs[128 * HST];

    const int tid  = threadIdx.x;
    const int lane = tid & 31;
    const int wid  = tid >> 5;
    const int g    = lane >> 2;
    const int t    = lane & 3;
    const int wm   = wid >> 2;
    const int wn   = wid & 3;

    const int rowBase = blockIdx.y * 128;
    const int colBase = blockIdx.x * 128;

    float4 aST[4], bST[4];
    const float* Ag = A + (size_t)rowBase * K;
    const float* Bg = B + (size_t)colBase * K;

    #pragma unroll
    for (int i = 0; i < 4; i++) {
        const int id = tid + i * 256;
        const int r  = id >> 3, c4 = (id & 7) * 4;
        aST[i] = *(const float4*)(Ag + (size_t)r * K + c4);
        bST[i] = *(const float4*)(Bg + (size_t)r * K + c4);
    }

    float acc[4][4][4];
    #pragma unroll
    for (int mi = 0; mi < 4; mi++)
        #pragma unroll
        for (int ni = 0; ni < 4; ni++)
            #pragma unroll
            for (int q = 0; q < 4; q++) acc[mi][ni][q] = 0.f;

    const int nIter = K / 32;
    for (int it = 0; it < nIter; it++) {
        #pragma unroll
        for (int i = 0; i < 4; i++) {
            const int id = tid + i * 256;
            const int r  = id >> 3, c4 = (id & 7) * 4;
            uint2 pa, pb;
            pa.x = h2u(__floats2half2_rn(aST[i].x, aST[i].y));
            pa.y = h2u(__floats2half2_rn(aST[i].z, aST[i].w));
            pb.x = h2u(__floats2half2_rn(bST[i].x, bST[i].y));
            pb.y = h2u(__floats2half2_rn(bST[i].z, bST[i].w));
            *(uint2*)(As + r * HST + c4) = pa;
            *(uint2*)(Bs + r * HST + c4) = pb;
        }
        __syncthreads();

        if (it + 1 < nIter) {
            const int k0 = (it + 1) * 32;
            #pragma unroll
            for (int i = 0; i < 4; i++) {
                const int id = tid + i * 256;
                const int r  = id >> 3, c4 = (id & 7) * 4;
                aST[i] = *(const float4*)(Ag + (size_t)r * K + k0 + c4);
                bST[i] = *(const float4*)(Bg + (size_t)r * K + k0 + c4);
            }
        }

        #pragma unroll
        for (int kk = 0; kk < 2; kk++) {
            uint32_t af[4][4], bf[4][2];
            #pragma unroll
            for (int mi = 0; mi < 4; mi++) {
                const int rb = wm * 64 + mi * 16;
                af[mi][0] = *(const uint32_t*)(As + (rb + g    ) * HST + kk * 16 + 2 * t    );
                af[mi][1] = *(const uint32_t*)(As + (rb + g + 8) * HST + kk * 16 + 2 * t    );
                af[mi][2] = *(const uint32_t*)(As + (rb + g    ) * HST + kk * 16 + 2 * t + 8);
                af[mi][3] = *(const uint32_t*)(As + (rb + g + 8) * HST + kk * 16 + 2 * t + 8);
            }
            #pragma unroll
            for (int ni = 0; ni < 4; ni++) {
                const int nb = wn * 32 + ni * 8;
                bf[ni][0] = *(const uint32_t*)(Bs + (nb + g) * HST + kk * 16 + 2 * t    );
                bf[ni][1] = *(const uint32_t*)(Bs + (nb + g) * HST + kk * 16 + 2 * t + 8);
            }
            #pragma unroll
            for (int mi = 0; mi < 4; mi++)
                #pragma unroll
                for (int ni = 0; ni < 4; ni++)
                    mma_f16(acc[mi][ni],
                            af[mi][0], af[mi][1], af[mi][2], af[mi][3],
                            bf[ni][0], bf[ni][1]);
        }
        __syncthreads();
    }

    #pragma unroll
    for (int mi = 0; mi < 4; mi++) {
        const int r0 = rowBase + wm * 64 + mi * 16 + g;
        #pragma unroll
        for (int ni = 0; ni < 4; ni++) {
            const int cidx = colBase + wn * 32 + ni * 8 + 2 * t;
            float b0 = 0.f, b1 = 0.f;
            if (bias) { b0 = bias[cidx]; b1 = bias[cidx + 1]; }
            float2 v01 = make_float2(acc[mi][ni][0] + b0, acc[mi][ni][1] + b1);
            float2 v23 = make_float2(acc[mi][ni][2] + b0, acc[mi][ni][3] + b1);
            *(float2*)(C + (size_t)r0 * N + cidx)       = v01;
            *(float2*)(C + (size_t)(r0 + 8) * N + cidx) = v23;
        }
    }
}

// ---------------------------------------------------------------------------
// FA2 flash attention, fp16 inputs (Q pre-scaled by 0.125*log2e in GEMM).
// BM=128, BN=64, 8 warps, warp tile 16x64. Smem stride 72 halfs.
// ---------------------------------------------------------------------------
#define ALD 72

__global__ __launch_bounds__(256) void attn_fa2h_kernel(
    const __half* __restrict__ Q, const __half* __restrict__ K,
    const __half* __restrict__ V, float* __restrict__ O)
{
    __shared__ __half Qs[128 * ALD];
    __shared__ __half Ks[ 64 * ALD];
    __shared__ __half Vt[ 64 * ALD];   // [dh][seq]

    const int tid  = threadIdx.x;
    const int lane = tid & 31;
    const int wid  = tid >> 5;
    const int g    = lane >> 2;
    const int t    = lane & 3;
    const int rb   = wid * 16;

    const int bh = blockIdx.y;
    const int b  = bh / NHEAD;
    const int h  = bh % NHEAD;
    const int q0 = blockIdx.x * 128;

    const __half* Qg = Q + (size_t)b * SEQ * DMODEL + h * DHEAD;
    const __half* Kg = K + (size_t)b * SEQ * DMODEL + h * DHEAD;
    const __half* Vg = V + (size_t)b * SEQ * DMODEL + h * DHEAD;

    // Q tile: 128 rows x 8 chunks(16B) = 1024 chunks
    #pragma unroll
    for (int i = 0; i < 4; i++) {
        const int ch = tid + i * 256;
        const int r = ch >> 3, c = ch & 7;
        *(uint4*)(Qs + r * ALD + c * 8) =
            *(const uint4*)(Qg + (size_t)(q0 + r) * DMODEL + c * 8);
    }

    float o[8][4];
    #pragma unroll
    for (int nj = 0; nj < 8; nj++)
        #pragma unroll
        for (int q = 0; q < 4; q++) o[nj][q] = 0.f;
    float m0 = -1e30f, m1 = -1e30f, l0 = 0.f, l1 = 0.f;

    for (int k0 = 0; k0 < SEQ; k0 += 64) {
        __syncthreads();

        // K tile: 64 rows x 8 chunks = 512
        #pragma unroll
        for (int i = 0; i < 2; i++) {
            const int ch = tid + i * 256;
            const int r = ch >> 3, c = ch & 7;
            *(uint4*)(Ks + r * ALD + c * 8) =
                *(const uint4*)(Kg + (size_t)(k0 + r) * DMODEL + c * 8);
        }
        // V transposed via byte_perm: Vt[d][seq-pair]
        #pragma unroll
        for (int i = 0; i < 2; i++) {
            const int id = tid + i * 256;        // 0..511
            const int d4 = id >> 5, p = id & 31; // d = 4*d4, s = 2*p
            const __half* r0p = Vg + (size_t)(k0 + 2 * p) * DMODEL + 4 * d4;
            uint2 v0 = *(const uint2*)(r0p);
            uint2 v1 = *(const uint2*)(r0p + DMODEL);
            *(uint32_t*)(Vt + (4 * d4 + 0) * ALD + 2 * p) = __byte_perm(v0.x, v1.x, 0x5410);
            *(uint32_t*)(Vt + (4 * d4 + 1) * ALD + 2 * p) = __byte_perm(v0.x, v1.x, 0x7632);
            *(uint32_t*)(Vt + (4 * d4 + 2) * ALD + 2 * p) = __byte_perm(v0.y, v1.y, 0x5410);
            *(uint32_t*)(Vt + (4 * d4 + 3) * ALD + 2 * p) = __byte_perm(v0.y, v1.y, 0x7632);
        }
        __syncthreads();

        // S = Q @ K^T (log2 domain; Q pre-scaled)
        float s[8][4];
        #pragma unroll
        for (int nj = 0; nj < 8; nj++)
            #pragma unroll
            for (int q = 0; q < 4; q++) s[nj][q] = 0.f;
        #pragma unroll
        for (int kk = 0; kk < 4; kk++) {
            const uint32_t a0 = *(const uint32_t*)(Qs + (rb + g    ) * ALD + kk * 16 + 2 * t    );
            const uint32_t a1 = *(const uint32_t*)(Qs + (rb + g + 8) * ALD + kk * 16 + 2 * t    );
            const uint32_t a2 = *(const uint32_t*)(Qs + (rb + g    ) * ALD + kk * 16 + 2 * t + 8);
            const uint32_t a3 = *(const uint32_t*)(Qs + (rb + g + 8) * ALD + kk * 16 + 2 * t + 8);
            #pragma unroll
            for (int nj = 0; nj < 8; nj++) {
                const uint32_t b0 = *(const uint32_t*)(Ks + (nj * 8 + g) * ALD + kk * 16 + 2 * t    );
                const uint32_t b1 = *(const uint32_t*)(Ks + (nj * 8 + g) * ALD + kk * 16 + 2 * t + 8);
                mma_f16(s[nj], a0, a1, a2, a3, b0, b1);
            }
        }

        // online softmax (rows g, g+8; quad lanes)
        float tm0 = -1e30f, tm1 = -1e30f;
        #pragma unroll
        for (int nj = 0; nj < 8; nj++) {
            tm0 = fmaxf(tm0, fmaxf(s[nj][0], s[nj][1]));
            tm1 = fmaxf(tm1, fmaxf(s[nj][2], s[nj][3]));
        }
        tm0 = fmaxf(tm0, __shfl_xor_sync(0xffffffffu, tm0, 1));
        tm0 = fmaxf(tm0, __shfl_xor_sync(0xffffffffu, tm0, 2));
        tm1 = fmaxf(tm1, __shfl_xor_sync(0xffffffffu, tm1, 1));
        tm1 = fmaxf(tm1, __shfl_xor_sync(0xffffffffu, tm1, 2));
        const float m0n = fmaxf(m0, tm0);
        const float m1n = fmaxf(m1, tm1);
        const float sc0 = exp2f(m0 - m0n);
        const float sc1 = exp2f(m1 - m1n);
        float sum0 = 0.f, sum1 = 0.f;
        #pragma unroll
        for (int nj = 0; nj < 8; nj++) {
            s[nj][0] = exp2f(s[nj][0] - m0n); sum0 += s[nj][0];
            s[nj][1] = exp2f(s[nj][1] - m0n); sum0 += s[nj][1];
            s[nj][2] = exp2f(s[nj][2] - m1n); sum1 += s[nj][2];
            s[nj][3] = exp2f(s[nj][3] - m1n); sum1 += s[nj][3];
        }
        sum0 += __shfl_xor_sync(0xffffffffu, sum0, 1);
        sum0 += __shfl_xor_sync(0xffffffffu, sum0, 2);
        sum1 += __shfl_xor_sync(0xffffffffu, sum1, 1);
        sum1 += __shfl_xor_sync(0xffffffffu, sum1, 2);
        l0 = l0 * sc0 + sum0;  m0 = m0n;
        l1 = l1 * sc1 + sum1;  m1 = m1n;
        #pragma unroll
        for (int nj = 0; nj < 8; nj++) {
            o[nj][0] *= sc0; o[nj][1] *= sc0;
            o[nj][2] *= sc1; o[nj][3] *= sc1;
        }

        // O += P @ V
        #pragma unroll
        for (int kc = 0; kc < 4; kc++) {
            const uint32_t a0 = h2u(__floats2half2_rn(s[2 * kc    ][0], s[2 * kc    ][1]));
            const uint32_t a1 = h2u(__floats2half2_rn(s[2 * kc    ][2], s[2 * kc    ][3]));
            const uint32_t a2 = h2u(__floats2half2_rn(s[2 * kc + 1][0], s[2 * kc + 1][1]));
            const uint32_t a3 = h2u(__floats2half2_rn(s[2 * kc + 1][2], s[2 * kc + 1][3]));
            #pragma unroll
            for (int nj = 0; nj < 8; nj++) {
                const uint32_t b0 = *(const uint32_t*)(Vt + (nj * 8 + g) * ALD + kc * 16 + 2 * t    );
                const uint32_t b1 = *(const uint32_t*)(Vt + (nj * 8 + g) * ALD + kc * 16 + 2 * t + 8);
                mma_f16(o[nj], a0, a1, a2, a3, b0, b1);
            }
        }
    }

    const float li0 = 1.f / l0;
    const float li1 = 1.f / l1;
    float* Og = O + (size_t)b * SEQ * DMODEL + h * DHEAD;
    #pragma unroll
    for (int nj = 0; nj < 8; nj++) {
        const int c = nj * 8 + 2 * t;
        *(float2*)(Og + (size_t)(q0 + rb + g    ) * DMODEL + c) =
            make_float2(o[nj][0] * li0, o[nj][1] * li0);
        *(float2*)(Og + (size_t)(q0 + rb + g + 8) * DMODEL + c) =
            make_float2(o[nj][2] * li1, o[nj][3] * li1);
    }
}

// ---------------------------------------------------------------------------
// Launch
// ---------------------------------------------------------------------------
extern "C" void kernel_launch(void* const* d_in, const int* in_sizes, int n_in,
                              void* d_out, int out_size)
{
    const float* z   = (const float*)d_in[0];
    const float* w_q = (const float*)d_in[1];
    const float* w_k = (const float*)d_in[2];
    const float* w_v = (const float*)d_in[3];
    const float* w_o = (const float*)d_in[4];
    const float* b_o = (const float*)d_in[5];
    float* out = (float*)d_out;

    const __half *zh, *Qh, *Kh, *Vh;
    float* AOp;
    cudaGetSymbolAddress((void**)&zh,  g_zh);
    cudaGetSymbolAddress((void**)&Qh,  g_Qh);
    cudaGetSymbolAddress((void**)&Kh,  g_Kh);
    cudaGetSymbolAddress((void**)&Vh,  g_Vh);
    cudaGetSymbolAddress((void**)&AOp, g_AO);

    const int qkvSmem = PSTG * 2 * STGH * (int)sizeof(__half);   // 61440
    static bool attrSet = false;
    if (!attrSet) {
        cudaFuncSetAttribute(gemm_qkv_kernel,
                             cudaFuncAttributeMaxDynamicSharedMemorySize,
                             qkvSmem);
        attrSet = true;
    }

    // 1. fp32 -> fp16 conversions (z + 3 weights)
    const int nTot4 = NZ4 + 3 * NW4;
    cvt_all_kernel<<<(nTot4 + 255) / 256, 256>>>(z, w_q, w_k, w_v);

    // 2. fused QKV projections (fp16 in/out, Q pre-scaled)
    const float QSCALE = 0.125f * 1.4426950408889634f;
    gemm_qkv_kernel<<<dim3(DMODEL / 128, MTOT / 128, 3), 256, qkvSmem>>>(
        zh, MTOT, DMODEL, DMODEL, QSCALE);

    // 3. attention
    attn_fa2h_kernel<<<dim3(SEQ / 128, BATCH * NHEAD), 256>>>(Qh, Kh, Vh, AOp);

    // 4. output projection (fp32 staging path)
    gemm_f16_kernel<<<dim3(DMODEL / 128, MTOT / 128), 256>>>(
        AOp, w_o, b_o, out, MTOT, DMODEL, DMODEL);
}

// round 12
// speedup vs baseline: 8.9875x; 1.2616x over previous
#include <cuda_runtime.h>
#include <cuda_fp16.h>
#include <math.h>
#include <stdint.h>

#define BATCH   8
#define SEQ     1024
#define DMODEL  768
#define NHEAD   12
#define DHEAD   64
#define MTOT    (BATCH * SEQ)   // 8192

// fp16 scratch
__device__ __half g_zh [MTOT * DMODEL];
__device__ __half g_wqh[DMODEL * DMODEL];
__device__ __half g_wkh[DMODEL * DMODEL];
__device__ __half g_wvh[DMODEL * DMODEL];
__device__ __half g_woh[DMODEL * DMODEL];
__device__ __half g_Qh [MTOT * DMODEL];
__device__ __half g_Kh [MTOT * DMODEL];
__device__ __half g_Vh [MTOT * DMODEL];
__device__ __half g_AOh[MTOT * DMODEL];

// ---------------------------------------------------------------------------
// Helpers
// ---------------------------------------------------------------------------
__device__ __forceinline__ void mma_f16(float c[4],
    uint32_t a0, uint32_t a1, uint32_t a2, uint32_t a3,
    uint32_t b0, uint32_t b1)
{
    asm volatile(
        "mma.sync.aligned.m16n8k16.row.col.f32.f16.f16.f32 "
        "{%0,%1,%2,%3}, {%4,%5,%6,%7}, {%8,%9}, {%0,%1,%2,%3};"
        : "+f"(c[0]), "+f"(c[1]), "+f"(c[2]), "+f"(c[3])
        : "r"(a0), "r"(a1), "r"(a2), "r"(a3), "r"(b0), "r"(b1));
}

__device__ __forceinline__ uint32_t h2u(__half2 h) {
    return *reinterpret_cast<uint32_t*>(&h);
}

__device__ __forceinline__ void cp_async16(void* smem_dst, const void* gmem_src) {
    uint32_t s = (uint32_t)__cvta_generic_to_shared(smem_dst);
    asm volatile("cp.async.cg.shared.global [%0], [%1], 16;\n"
                 :: "r"(s), "l"(gmem_src));
}

__device__ __forceinline__ void ldsm_x4(
    uint32_t& d0, uint32_t& d1, uint32_t& d2, uint32_t& d3, uint32_t addr)
{
    asm volatile("ldmatrix.sync.aligned.m8n8.x4.shared.b16 {%0,%1,%2,%3}, [%4];"
                 : "=r"(d0), "=r"(d1), "=r"(d2), "=r"(d3) : "r"(addr));
}

__device__ __forceinline__ void ldsm_x4_t(
    uint32_t& d0, uint32_t& d1, uint32_t& d2, uint32_t& d3, uint32_t addr)
{
    asm volatile("ldmatrix.sync.aligned.m8n8.x4.trans.shared.b16 {%0,%1,%2,%3}, [%4];"
                 : "=r"(d0), "=r"(d1), "=r"(d2), "=r"(d3) : "r"(addr));
}

// ---------------------------------------------------------------------------
// fp32 -> fp16 conversion (z + 4 weights in one launch)
// ---------------------------------------------------------------------------
#define NZ4 ((MTOT * DMODEL) / 4)        // 1572864
#define NW4 ((DMODEL * DMODEL) / 4)      // 147456

__global__ __launch_bounds__(256) void cvt_all_kernel(
    const float* __restrict__ z,  const float* __restrict__ wq,
    const float* __restrict__ wk, const float* __restrict__ wv,
    const float* __restrict__ wo)
{
    const int i = blockIdx.x * 256 + threadIdx.x;
    const float* src; __half* dst; int idx;
    if (i < NZ4)                { src = z;  dst = g_zh;  idx = i; }
    else if (i < NZ4 +   NW4)   { src = wq; dst = g_wqh; idx = i - NZ4; }
    else if (i < NZ4 + 2*NW4)   { src = wk; dst = g_wkh; idx = i - NZ4 - NW4; }
    else if (i < NZ4 + 3*NW4)   { src = wv; dst = g_wvh; idx = i - NZ4 - 2*NW4; }
    else if (i < NZ4 + 4*NW4)   { src = wo; dst = g_woh; idx = i - NZ4 - 3*NW4; }
    else return;
    float4 v = ((const float4*)src)[idx];
    uint2 p;
    p.x = h2u(__floats2half2_rn(v.x, v.y));
    p.y = h2u(__floats2half2_rn(v.z, v.w));
    ((uint2*)dst)[idx] = p;
}

// ---------------------------------------------------------------------------
// Fused QKV GEMM (NT, fp16 in / fp16 out): 3-stage cp.async pipeline.
// ---------------------------------------------------------------------------
#define HST   40
#define PSTG  3
#define STGH  (128 * HST)

__global__ __launch_bounds__(256) void gemm_qkv_kernel(
    const __half* __restrict__ A, int M, int N, int K, float qscale)
{
    extern __shared__ __half sh[];
    __half* As = sh;
    __half* Bs = sh + PSTG * STGH;

    const __half* B; __half* C; float outScale;
    if      (blockIdx.z == 0) { B = g_wqh; C = g_Qh; outScale = qscale; }
    else if (blockIdx.z == 1) { B = g_wkh; C = g_Kh; outScale = 1.f; }
    else                      { B = g_wvh; C = g_Vh; outScale = 1.f; }

    const int tid  = threadIdx.x;
    const int lane = tid & 31;
    const int wid  = tid >> 5;
    const int g    = lane >> 2;
    const int t    = lane & 3;
    const int wm   = wid >> 2;
    const int wn   = wid & 3;

    const int rowBase = blockIdx.y * 128;
    const int colBase = blockIdx.x * 128;
    const __half* Ag = A + (size_t)rowBase * K;
    const __half* Bg = B + (size_t)colBase * K;

    auto issue = [&](int st) {
        const int buf = st % PSTG;
        const int k0  = st * 32;
        #pragma unroll
        for (int i = 0; i < 2; i++) {
            const int ch = tid + i * 256;
            const int r = ch >> 2, c = ch & 3;
            cp_async16(As + buf * STGH + r * HST + c * 8,
                       Ag + (size_t)r * K + k0 + c * 8);
            cp_async16(Bs + buf * STGH + r * HST + c * 8,
                       Bg + (size_t)r * K + k0 + c * 8);
        }
    };

    float acc[4][4][4];
    #pragma unroll
    for (int mi = 0; mi < 4; mi++)
        #pragma unroll
        for (int ni = 0; ni < 4; ni++)
            #pragma unroll
            for (int q = 0; q < 4; q++) acc[mi][ni][q] = 0.f;

    issue(0); asm volatile("cp.async.commit_group;" ::: "memory");
    issue(1); asm volatile("cp.async.commit_group;" ::: "memory");

    const int kIter = K / 32;
    for (int it = 0; it < kIter; it++) {
        asm volatile("cp.async.wait_group 1;" ::: "memory");
        __syncthreads();

        if (it + 2 < kIter) issue(it + 2);
        asm volatile("cp.async.commit_group;" ::: "memory");

        const __half* Ab = As + (it % PSTG) * STGH;
        const __half* Bb = Bs + (it % PSTG) * STGH;

        #pragma unroll
        for (int kk = 0; kk < 2; kk++) {
            uint32_t af[4][4], bf[4][2];
            #pragma unroll
            for (int mi = 0; mi < 4; mi++) {
                const int rb = wm * 64 + mi * 16;
                af[mi][0] = *(const uint32_t*)(Ab + (rb + g    ) * HST + kk * 16 + 2 * t    );
                af[mi][1] = *(const uint32_t*)(Ab + (rb + g + 8) * HST + kk * 16 + 2 * t    );
                af[mi][2] = *(const uint32_t*)(Ab + (rb + g    ) * HST + kk * 16 + 2 * t + 8);
                af[mi][3] = *(const uint32_t*)(Ab + (rb + g + 8) * HST + kk * 16 + 2 * t + 8);
            }
            #pragma unroll
            for (int ni = 0; ni < 4; ni++) {
                const int nb = wn * 32 + ni * 8;
                bf[ni][0] = *(const uint32_t*)(Bb + (nb + g) * HST + kk * 16 + 2 * t    );
                bf[ni][1] = *(const uint32_t*)(Bb + (nb + g) * HST + kk * 16 + 2 * t + 8);
            }
            #pragma unroll
            for (int mi = 0; mi < 4; mi++)
                #pragma unroll
                for (int ni = 0; ni < 4; ni++)
                    mma_f16(acc[mi][ni],
                            af[mi][0], af[mi][1], af[mi][2], af[mi][3],
                            bf[ni][0], bf[ni][1]);
        }
        __syncthreads();
    }

    #pragma unroll
    for (int mi = 0; mi < 4; mi++) {
        const int r0 = rowBase + wm * 64 + mi * 16 + g;
        #pragma unroll
        for (int ni = 0; ni < 4; ni++) {
            const int cidx = colBase + wn * 32 + ni * 8 + 2 * t;
            *(uint32_t*)(C + (size_t)r0 * N + cidx) =
                h2u(__floats2half2_rn(acc[mi][ni][0] * outScale, acc[mi][ni][1] * outScale));
            *(uint32_t*)(C + (size_t)(r0 + 8) * N + cidx) =
                h2u(__floats2half2_rn(acc[mi][ni][2] * outScale, acc[mi][ni][3] * outScale));
        }
    }
}

// ---------------------------------------------------------------------------
// O projection GEMM (NT, fp16 in / fp32+bias out): 3-stage cp.async pipeline.
// ---------------------------------------------------------------------------
__global__ __launch_bounds__(256) void gemm_out_kernel(
    const __half* __restrict__ A, const __half* __restrict__ B,
    const float* __restrict__ bias, float* __restrict__ C,
    int M, int N, int K)
{
    extern __shared__ __half sh[];
    __half* As = sh;
    __half* Bs = sh + PSTG * STGH;

    const int tid  = threadIdx.x;
    const int lane = tid & 31;
    const int wid  = tid >> 5;
    const int g    = lane >> 2;
    const int t    = lane & 3;
    const int wm   = wid >> 2;
    const int wn   = wid & 3;

    const int rowBase = blockIdx.y * 128;
    const int colBase = blockIdx.x * 128;
    const __half* Ag = A + (size_t)rowBase * K;
    const __half* Bg = B + (size_t)colBase * K;

    auto issue = [&](int st) {
        const int buf = st % PSTG;
        const int k0  = st * 32;
        #pragma unroll
        for (int i = 0; i < 2; i++) {
            const int ch = tid + i * 256;
            const int r = ch >> 2, c = ch & 3;
            cp_async16(As + buf * STGH + r * HST + c * 8,
                       Ag + (size_t)r * K + k0 + c * 8);
            cp_async16(Bs + buf * STGH + r * HST + c * 8,
                       Bg + (size_t)r * K + k0 + c * 8);
        }
    };

    float acc[4][4][4];
    #pragma unroll
    for (int mi = 0; mi < 4; mi++)
        #pragma unroll
        for (int ni = 0; ni < 4; ni++)
            #pragma unroll
            for (int q = 0; q < 4; q++) acc[mi][ni][q] = 0.f;

    issue(0); asm volatile("cp.async.commit_group;" ::: "memory");
    issue(1); asm volatile("cp.async.commit_group;" ::: "memory");

    const int kIter = K / 32;
    for (int it = 0; it < kIter; it++) {
        asm volatile("cp.async.wait_group 1;" ::: "memory");
        __syncthreads();

        if (it + 2 < kIter) issue(it + 2);
        asm volatile("cp.async.commit_group;" ::: "memory");

        const __half* Ab = As + (it % PSTG) * STGH;
        const __half* Bb = Bs + (it % PSTG) * STGH;

        #pragma unroll
        for (int kk = 0; kk < 2; kk++) {
            uint32_t af[4][4], bf[4][2];
            #pragma unroll
            for (int mi = 0; mi < 4; mi++) {
                const int rb = wm * 64 + mi * 16;
                af[mi][0] = *(const uint32_t*)(Ab + (rb + g    ) * HST + kk * 16 + 2 * t    );
                af[mi][1] = *(const uint32_t*)(Ab + (rb + g + 8) * HST + kk * 16 + 2 * t    );
                af[mi][2] = *(const uint32_t*)(Ab + (rb + g    ) * HST + kk * 16 + 2 * t + 8);
                af[mi][3] = *(const uint32_t*)(Ab + (rb + g + 8) * HST + kk * 16 + 2 * t + 8);
            }
            #pragma unroll
            for (int ni = 0; ni < 4; ni++) {
                const int nb = wn * 32 + ni * 8;
                bf[ni][0] = *(const uint32_t*)(Bb + (nb + g) * HST + kk * 16 + 2 * t    );
                bf[ni][1] = *(const uint32_t*)(Bb + (nb + g) * HST + kk * 16 + 2 * t + 8);
            }
            #pragma unroll
            for (int mi = 0; mi < 4; mi++)
                #pragma unroll
                for (int ni = 0; ni < 4; ni++)
                    mma_f16(acc[mi][ni],
                            af[mi][0], af[mi][1], af[mi][2], af[mi][3],
                            bf[ni][0], bf[ni][1]);
        }
        __syncthreads();
    }

    #pragma unroll
    for (int mi = 0; mi < 4; mi++) {
        const int r0 = rowBase + wm * 64 + mi * 16 + g;
        #pragma unroll
        for (int ni = 0; ni < 4; ni++) {
            const int cidx = colBase + wn * 32 + ni * 8 + 2 * t;
            const float b0 = bias[cidx], b1 = bias[cidx + 1];
            *(float2*)(C + (size_t)r0 * N + cidx) =
                make_float2(acc[mi][ni][0] + b0, acc[mi][ni][1] + b1);
            *(float2*)(C + (size_t)(r0 + 8) * N + cidx) =
                make_float2(acc[mi][ni][2] + b0, acc[mi][ni][3] + b1);
        }
    }
}

// ---------------------------------------------------------------------------
// FA2 flash attention: fp16 in/out, cp.async 3-deep K/V pipeline, ldmatrix
// fragment loads (V transposed by ldmatrix.trans — stored row-major).
// BM=128, BN=64, 8 warps, warp tile 16x64. Stride 72 halfs (144B):
// LDSM phase rows hit word-banks 4r mod 32 -> conflict-free.
// ---------------------------------------------------------------------------
#define ALD 72

__global__ __launch_bounds__(256) void attn_fa2p_kernel(
    const __half* __restrict__ Q, const __half* __restrict__ K,
    const __half* __restrict__ V, __half* __restrict__ O)
{
    extern __shared__ __half sm[];
    __half* Qs = sm;                       // 128 x 72
    __half* Ks = Qs + 128 * ALD;           // 3 x (64 x 72)
    __half* Vs = Ks + 3 * 64 * ALD;        // 3 x (64 x 72)

    const int tid  = threadIdx.x;
    const int lane = tid & 31;
    const int wid  = tid >> 5;
    const int g    = lane >> 2;
    const int t    = lane & 3;
    const int rb   = wid * 16;

    const int bh = blockIdx.y;
    const int b  = bh / NHEAD;
    const int h  = bh % NHEAD;
    const int q0 = blockIdx.x * 128;

    const __half* Qg = Q + (size_t)b * SEQ * DMODEL + h * DHEAD;
    const __half* Kg = K + (size_t)b * SEQ * DMODEL + h * DHEAD;
    const __half* Vg = V + (size_t)b * SEQ * DMODEL + h * DHEAD;

    // ldmatrix lane-address components
    const int qr = lane & 15,                 qc = (lane >> 4) * 8;          // Q (A-frag)
    const int kr = (lane & 7) + ((lane >> 4) << 3), kc2 = ((lane >> 3) & 1) << 3; // K (B-frag)
    const int vr = (lane & 7) + (((lane >> 3) & 1) << 3), vc = (lane >> 4) << 3;  // V (B-frag trans)

    // Q tile load (plain LDG/STS, once)
    #pragma unroll
    for (int i = 0; i < 4; i++) {
        const int ch = tid + i * 256;
        const int r = ch >> 3, c = ch & 7;
        *(uint4*)(Qs + r * ALD + c * 8) =
            *(const uint4*)(Qg + (size_t)(q0 + r) * DMODEL + c * 8);
    }

    // K/V chunk issue (cp.async; always commit, even when empty)
    auto issueKV = [&](int st) {
        if (st < SEQ / 64) {
            __half* kb = Ks + (st % 3) * 64 * ALD;
            __half* vb = Vs + (st % 3) * 64 * ALD;
            const int k0 = st * 64;
            #pragma unroll
            for (int i = 0; i < 2; i++) {
                const int ch = tid + i * 256;
                const int r = ch >> 3, c = ch & 7;
                cp_async16(kb + r * ALD + c * 8, Kg + (size_t)(k0 + r) * DMODEL + c * 8);
                cp_async16(vb + r * ALD + c * 8, Vg + (size_t)(k0 + r) * DMODEL + c * 8);
            }
        }
        asm volatile("cp.async.commit_group;" ::: "memory");
    };

    issueKV(0);
    issueKV(1);

    float o[8][4];
    #pragma unroll
    for (int nj = 0; nj < 8; nj++)
        #pragma unroll
        for (int q = 0; q < 4; q++) o[nj][q] = 0.f;
    float m0 = -1e30f, m1 = -1e30f, l0 = 0.f, l1 = 0.f;

    for (int ic = 0; ic < SEQ / 64; ic++) {
        asm volatile("cp.async.wait_group 1;" ::: "memory");
        __syncthreads();
        issueKV(ic + 2);

        const __half* Kb = Ks + (ic % 3) * 64 * ALD;
        const __half* Vb = Vs + (ic % 3) * 64 * ALD;

        // S = Q @ K^T (log2 domain; Q pre-scaled by 0.125*log2e in GEMM)
        float s[8][4];
        #pragma unroll
        for (int nj = 0; nj < 8; nj++)
            #pragma unroll
            for (int q = 0; q < 4; q++) s[nj][q] = 0.f;
        #pragma unroll
        for (int kk = 0; kk < 4; kk++) {
            uint32_t a0, a1, a2, a3;
            ldsm_x4(a0, a1, a2, a3,
                (uint32_t)__cvta_generic_to_shared(Qs + (rb + qr) * ALD + kk * 16 + qc));
            #pragma unroll
            for (int njp = 0; njp < 4; njp++) {
                uint32_t b0, b1, b2, b3;
                ldsm_x4(b0, b1, b2, b3,
                    (uint32_t)__cvta_generic_to_shared(Kb + (njp * 16 + kr) * ALD + kk * 16 + kc2));
                mma_f16(s[njp * 2    ], a0, a1, a2, a3, b0, b1);
                mma_f16(s[njp * 2 + 1], a0, a1, a2, a3, b2, b3);
            }
        }

        // online softmax (rows g, g+8; quad lanes)
        float tm0 = -1e30f, tm1 = -1e30f;
        #pragma unroll
        for (int nj = 0; nj < 8; nj++) {
            tm0 = fmaxf(tm0, fmaxf(s[nj][0], s[nj][1]));
            tm1 = fmaxf(tm1, fmaxf(s[nj][2], s[nj][3]));
        }
        tm0 = fmaxf(tm0, __shfl_xor_sync(0xffffffffu, tm0, 1));
        tm0 = fmaxf(tm0, __shfl_xor_sync(0xffffffffu, tm0, 2));
        tm1 = fmaxf(tm1, __shfl_xor_sync(0xffffffffu, tm1, 1));
        tm1 = fmaxf(tm1, __shfl_xor_sync(0xffffffffu, tm1, 2));
        const float m0n = fmaxf(m0, tm0);
        const float m1n = fmaxf(m1, tm1);
        const float sc0 = exp2f(m0 - m0n);
        const float sc1 = exp2f(m1 - m1n);
        float sum0 = 0.f, sum1 = 0.f;
        #pragma unroll
        for (int nj = 0; nj < 8; nj++) {
            s[nj][0] = exp2f(s[nj][0] - m0n); sum0 += s[nj][0];
            s[nj][1] = exp2f(s[nj][1] - m0n); sum0 += s[nj][1];
            s[nj][2] = exp2f(s[nj][2] - m1n); sum1 += s[nj][2];
            s[nj][3] = exp2f(s[nj][3] - m1n); sum1 += s[nj][3];
        }
        sum0 += __shfl_xor_sync(0xffffffffu, sum0, 1);
        sum0 += __shfl_xor_sync(0xffffffffu, sum0, 2);
        sum1 += __shfl_xor_sync(0xffffffffu, sum1, 1);
        sum1 += __shfl_xor_sync(0xffffffffu, sum1, 2);
        l0 = l0 * sc0 + sum0;  m0 = m0n;
        l1 = l1 * sc1 + sum1;  m1 = m1n;
        #pragma unroll
        for (int nj = 0; nj < 8; nj++) {
            o[nj][0] *= sc0; o[nj][1] *= sc0;
            o[nj][2] *= sc1; o[nj][3] *= sc1;
        }

        // O += P @ V  (V row-major; B-frags via ldmatrix.trans)
        #pragma unroll
        for (int kcI = 0; kcI < 4; kcI++) {
            const uint32_t a0 = h2u(__floats2half2_rn(s[2 * kcI    ][0], s[2 * kcI    ][1]));
            const uint32_t a1 = h2u(__floats2half2_rn(s[2 * kcI    ][2], s[2 * kcI    ][3]));
            const uint32_t a2 = h2u(__floats2half2_rn(s[2 * kcI + 1][0], s[2 * kcI + 1][1]));
            const uint32_t a3 = h2u(__floats2half2_rn(s[2 * kcI + 1][2], s[2 * kcI + 1][3]));
            #pragma unroll
            for (int njp = 0; njp < 4; njp++) {
                uint32_t b0, b1, b2, b3;
                ldsm_x4_t(b0, b1, b2, b3,
                    (uint32_t)__cvta_generic_to_shared(Vb + (kcI * 16 + vr) * ALD + njp * 16 + vc));
                mma_f16(o[njp * 2    ], a0, a1, a2, a3, b0, b1);
                mma_f16(o[njp * 2 + 1], a0, a1, a2, a3, b2, b3);
            }
        }
    }

    // epilogue: normalize, store fp16
    const float li0 = 1.f / l0;
    const float li1 = 1.f / l1;
    __half* Og = O + (size_t)b * SEQ * DMODEL + h * DHEAD;
    #pragma unroll
    for (int nj = 0; nj < 8; nj++) {
        const int c = nj * 8 + 2 * t;
        *(uint32_t*)(Og + (size_t)(q0 + rb + g    ) * DMODEL + c) =
            h2u(__floats2half2_rn(o[nj][0] * li0, o[nj][1] * li0));
        *(uint32_t*)(Og + (size_t)(q0 + rb + g + 8) * DMODEL + c) =
            h2u(__floats2half2_rn(o[nj][2] * li1, o[nj][3] * li1));
    }
}

// ---------------------------------------------------------------------------
// Launch
// ---------------------------------------------------------------------------
extern "C" void kernel_launch(void* const* d_in, const int* in_sizes, int n_in,
                              void* d_out, int out_size)
{
    const float* z   = (const float*)d_in[0];
    const float* w_q = (const float*)d_in[1];
    const float* w_k = (const float*)d_in[2];
    const float* w_v = (const float*)d_in[3];
    const float* w_o = (const float*)d_in[4];
    const float* b_o = (const float*)d_in[5];
    float* out = (float*)d_out;

    const __half *zh, *Qh, *Kh, *Vh, *woh;
    __half* AOh;
    cudaGetSymbolAddress((void**)&zh,  g_zh);
    cudaGetSymbolAddress((void**)&Qh,  g_Qh);
    cudaGetSymbolAddress((void**)&Kh,  g_Kh);
    cudaGetSymbolAddress((void**)&Vh,  g_Vh);
    cudaGetSymbolAddress((void**)&woh, g_woh);
    cudaGetSymbolAddress((void**)&AOh, g_AOh);

    const int qkvSmem  = PSTG * 2 * STGH * (int)sizeof(__half);            // 61440
    const int attnSmem = (128 * ALD + 6 * 64 * ALD) * (int)sizeof(__half); // 73728
    static bool attrSet = false;
    if (!attrSet) {
        cudaFuncSetAttribute(gemm_qkv_kernel,
                             cudaFuncAttributeMaxDynamicSharedMemorySize, qkvSmem);
        cudaFuncSetAttribute(gemm_out_kernel,
                             cudaFuncAttributeMaxDynamicSharedMemorySize, qkvSmem);
        cudaFuncSetAttribute(attn_fa2p_kernel,
                             cudaFuncAttributeMaxDynamicSharedMemorySize, attnSmem);
        attrSet = true;
    }

    // 1. fp32 -> fp16 conversions (z + 4 weights)
    const int nTot4 = NZ4 + 4 * NW4;
    cvt_all_kernel<<<(nTot4 + 255) / 256, 256>>>(z, w_q, w_k, w_v, w_o);

    // 2. fused QKV projections (Q pre-scaled by 1/8 * log2e)
    const float QSCALE = 0.125f * 1.4426950408889634f;
    gemm_qkv_kernel<<<dim3(DMODEL / 128, MTOT / 128, 3), 256, qkvSmem>>>(
        zh, MTOT, DMODEL, DMODEL, QSCALE);

    // 3. attention (fp16 out)
    attn_fa2p_kernel<<<dim3(SEQ / 128, BATCH * NHEAD), 256, attnSmem>>>(
        Qh, Kh, Vh, AOh);

    // 4. output projection (pipelined, fp32 + bias out)
    gemm_out_kernel<<<dim3(DMODEL / 128, MTOT / 128), 256, qkvSmem>>>(
        AOh, woh, b_o, out, MTOT, DMODEL, DMODEL);
}

// round 14
// speedup vs baseline: 9.6251x; 1.0709x over previous
#include <cuda_runtime.h>
#include <cuda_fp16.h>
#include <math.h>
#include <stdint.h>

#define BATCH   8
#define SEQ     1024
#define DMODEL  768
#define NHEAD   12
#define DHEAD   64
#define MTOT    (BATCH * SEQ)   // 8192

// fp16 scratch
__device__ __half g_zh [MTOT * DMODEL];
__device__ __half g_wqh[DMODEL * DMODEL];
__device__ __half g_wkh[DMODEL * DMODEL];
__device__ __half g_wvh[DMODEL * DMODEL];
__device__ __half g_woh[DMODEL * DMODEL];
__device__ __half g_Qh [MTOT * DMODEL];
__device__ __half g_Kh [MTOT * DMODEL];
__device__ __half g_Vh [MTOT * DMODEL];
__device__ __half g_AOh[MTOT * DMODEL];

// ---------------------------------------------------------------------------
// Helpers
// ---------------------------------------------------------------------------
__device__ __forceinline__ void mma_f16(float c[4],
    uint32_t a0, uint32_t a1, uint32_t a2, uint32_t a3,
    uint32_t b0, uint32_t b1)
{
    asm volatile(
        "mma.sync.aligned.m16n8k16.row.col.f32.f16.f16.f32 "
        "{%0,%1,%2,%3}, {%4,%5,%6,%7}, {%8,%9}, {%0,%1,%2,%3};"
        : "+f"(c[0]), "+f"(c[1]), "+f"(c[2]), "+f"(c[3])
        : "r"(a0), "r"(a1), "r"(a2), "r"(a3), "r"(b0), "r"(b1));
}

__device__ __forceinline__ uint32_t h2u(__half2 h) {
    return *reinterpret_cast<uint32_t*>(&h);
}

__device__ __forceinline__ void cp_async16(void* smem_dst, const void* gmem_src) {
    uint32_t s = (uint32_t)__cvta_generic_to_shared(smem_dst);
    asm volatile("cp.async.cg.shared.global [%0], [%1], 16;\n"
                 :: "r"(s), "l"(gmem_src));
}

__device__ __forceinline__ void ldsm_x4(
    uint32_t& d0, uint32_t& d1, uint32_t& d2, uint32_t& d3, uint32_t addr)
{
    asm volatile("ldmatrix.sync.aligned.m8n8.x4.shared.b16 {%0,%1,%2,%3}, [%4];"
                 : "=r"(d0), "=r"(d1), "=r"(d2), "=r"(d3) : "r"(addr));
}

__device__ __forceinline__ void ldsm_x4_t(
    uint32_t& d0, uint32_t& d1, uint32_t& d2, uint32_t& d3, uint32_t addr)
{
    asm volatile("ldmatrix.sync.aligned.m8n8.x4.trans.shared.b16 {%0,%1,%2,%3}, [%4];"
                 : "=r"(d0), "=r"(d1), "=r"(d2), "=r"(d3) : "r"(addr));
}

// ---------------------------------------------------------------------------
// fp32 -> fp16 conversion (z + 4 weights in one launch)
// ---------------------------------------------------------------------------
#define NZ4 ((MTOT * DMODEL) / 4)
#define NW4 ((DMODEL * DMODEL) / 4)

__global__ __launch_bounds__(256) void cvt_all_kernel(
    const float* __restrict__ z,  const float* __restrict__ wq,
    const float* __restrict__ wk, const float* __restrict__ wv,
    const float* __restrict__ wo)
{
    const int i = blockIdx.x * 256 + threadIdx.x;
    const float* src; __half* dst; int idx;
    if (i < NZ4)                { src = z;  dst = g_zh;  idx = i; }
    else if (i < NZ4 +   NW4)   { src = wq; dst = g_wqh; idx = i - NZ4; }
    else if (i < NZ4 + 2*NW4)   { src = wk; dst = g_wkh; idx = i - NZ4 - NW4; }
    else if (i < NZ4 + 3*NW4)   { src = wv; dst = g_wvh; idx = i - NZ4 - 2*NW4; }
    else if (i < NZ4 + 4*NW4)   { src = wo; dst = g_woh; idx = i - NZ4 - 3*NW4; }
    else return;
    float4 v = ((const float4*)src)[idx];
    uint2 p;
    p.x = h2u(__floats2half2_rn(v.x, v.y));
    p.y = h2u(__floats2half2_rn(v.z, v.w));
    ((uint2*)dst)[idx] = p;
}

// ---------------------------------------------------------------------------
// Shared GEMM mainloop pieces (128x128 tile, BK=32, 3-stage cp.async,
// ldmatrix fragment loads). HST=40 halfs: LDSM phase rows hit word-banks
// 20r mod 32 (distinct for r=0..7) -> conflict-free.
// ---------------------------------------------------------------------------
#define HST   40
#define PSTG  3
#define STGH  (128 * HST)

// fragment compute for one BK=32 stage (both kk halves)
#define GEMM_STAGE_COMPUTE(Ab, Bb)                                            \
    _Pragma("unroll")                                                         \
    for (int kk = 0; kk < 2; kk++) {                                          \
        uint32_t af[4][4], bf[4][2];                                          \
        _Pragma("unroll")                                                     \
        for (int mi = 0; mi < 4; mi++) {                                      \
            const int rb2 = wm * 64 + mi * 16;                                \
            ldsm_x4(af[mi][0], af[mi][1], af[mi][2], af[mi][3],               \
                (uint32_t)__cvta_generic_to_shared(                           \
                    (Ab) + (rb2 + ar) * HST + kk * 16 + ac));                 \
        }                                                                     \
        _Pragma("unroll")                                                     \
        for (int np = 0; np < 2; np++) {                                      \
            uint32_t b0, b1, b2, b3;                                          \
            ldsm_x4(b0, b1, b2, b3,                                           \
                (uint32_t)__cvta_generic_to_shared(                           \
                    (Bb) + (wn * 32 + np * 16 + br) * HST + kk * 16 + bc));   \
            bf[np * 2    ][0] = b0; bf[np * 2    ][1] = b1;                   \
            bf[np * 2 + 1][0] = b2; bf[np * 2 + 1][1] = b3;                   \
        }                                                                     \
        _Pragma("unroll")                                                     \
        for (int mi = 0; mi < 4; mi++)                                        \
            _Pragma("unroll")                                                 \
            for (int ni = 0; ni < 4; ni++)                                    \
                mma_f16(acc[mi][ni],                                          \
                        af[mi][0], af[mi][1], af[mi][2], af[mi][3],           \
                        bf[ni][0], bf[ni][1]);                                \
    }

// ---------------------------------------------------------------------------
// Fused QKV GEMM (NT, fp16 in / fp16 out)
// ---------------------------------------------------------------------------
__global__ __launch_bounds__(256, 2) void gemm_qkv_kernel(
    const __half* __restrict__ A, int M, int N, int K, float qscale)
{
    extern __shared__ __half sh[];
    __half* As = sh;
    __half* Bs = sh + PSTG * STGH;

    const __half* B; __half* C; float outScale;
    if      (blockIdx.z == 0) { B = g_wqh; C = g_Qh; outScale = qscale; }
    else if (blockIdx.z == 1) { B = g_wkh; C = g_Kh; outScale = 1.f; }
    else                      { B = g_wvh; C = g_Vh; outScale = 1.f; }

    const int tid  = threadIdx.x;
    const int lane = tid & 31;
    const int wid  = tid >> 5;
    const int g    = lane >> 2;
    const int t    = lane & 3;
    const int wm   = wid >> 2;
    const int wn   = wid & 3;

    // ldmatrix lane address components
    const int ar = lane & 15,                      ac = (lane >> 4) * 8;        // A-frag
    const int br = (lane & 7) + ((lane >> 4) << 3), bc = ((lane >> 3) & 1) << 3; // B-frag

    const int rowBase = blockIdx.y * 128;
    const int colBase = blockIdx.x * 128;
    const __half* Ag = A + (size_t)rowBase * K;
    const __half* Bg = B + (size_t)colBase * K;

    auto issue = [&](int st) {
        const int buf = st % PSTG;
        const int k0  = st * 32;
        #pragma unroll
        for (int i = 0; i < 2; i++) {
            const int ch = tid + i * 256;
            const int r = ch >> 2, c = ch & 3;
            cp_async16(As + buf * STGH + r * HST + c * 8,
                       Ag + (size_t)r * K + k0 + c * 8);
            cp_async16(Bs + buf * STGH + r * HST + c * 8,
                       Bg + (size_t)r * K + k0 + c * 8);
        }
    };

    float acc[4][4][4];
    #pragma unroll
    for (int mi = 0; mi < 4; mi++)
        #pragma unroll
        for (int ni = 0; ni < 4; ni++)
            #pragma unroll
            for (int q = 0; q < 4; q++) acc[mi][ni][q] = 0.f;

    issue(0); asm volatile("cp.async.commit_group;" ::: "memory");
    issue(1); asm volatile("cp.async.commit_group;" ::: "memory");

    const int kIter = K / 32;
    for (int it = 0; it < kIter; it++) {
        asm volatile("cp.async.wait_group 1;" ::: "memory");
        __syncthreads();

        if (it + 2 < kIter) issue(it + 2);
        asm volatile("cp.async.commit_group;" ::: "memory");

        const __half* Ab = As + (it % PSTG) * STGH;
        const __half* Bb = Bs + (it % PSTG) * STGH;
        GEMM_STAGE_COMPUTE(Ab, Bb)
        __syncthreads();
    }

    #pragma unroll
    for (int mi = 0; mi < 4; mi++) {
        const int r0 = rowBase + wm * 64 + mi * 16 + g;
        #pragma unroll
        for (int ni = 0; ni < 4; ni++) {
            const int cidx = colBase + wn * 32 + ni * 8 + 2 * t;
            *(uint32_t*)(C + (size_t)r0 * N + cidx) =
                h2u(__floats2half2_rn(acc[mi][ni][0] * outScale, acc[mi][ni][1] * outScale));
            *(uint32_t*)(C + (size_t)(r0 + 8) * N + cidx) =
                h2u(__floats2half2_rn(acc[mi][ni][2] * outScale, acc[mi][ni][3] * outScale));
        }
    }
}

// ---------------------------------------------------------------------------
// O projection GEMM (NT, fp16 in / fp32+bias out)
// ---------------------------------------------------------------------------
__global__ __launch_bounds__(256, 2) void gemm_out_kernel(
    const __half* __restrict__ A, const __half* __restrict__ B,
    const float* __restrict__ bias, float* __restrict__ C,
    int M, int N, int K)
{
    extern __shared__ __half sh[];
    __half* As = sh;
    __half* Bs = sh + PSTG * STGH;

    const int tid  = threadIdx.x;
    const int lane = tid & 31;
    const int wid  = tid >> 5;
    const int g    = lane >> 2;
    const int t    = lane & 3;
    const int wm   = wid >> 2;
    const int wn   = wid & 3;

    const int ar = lane & 15,                      ac = (lane >> 4) * 8;
    const int br = (lane & 7) + ((lane >> 4) << 3), bc = ((lane >> 3) & 1) << 3;

    const int rowBase = blockIdx.y * 128;
    const int colBase = blockIdx.x * 128;
    const __half* Ag = A + (size_t)rowBase * K;
    const __half* Bg = B + (size_t)colBase * K;

    auto issue = [&](int st) {
        const int buf = st % PSTG;
        const int k0  = st * 32;
        #pragma unroll
        for (int i = 0; i < 2; i++) {
            const int ch = tid + i * 256;
            const int r = ch >> 2, c = ch & 3;
            cp_async16(As + buf * STGH + r * HST + c * 8,
                       Ag + (size_t)r * K + k0 + c * 8);
            cp_async16(Bs + buf * STGH + r * HST + c * 8,
                       Bg + (size_t)r * K + k0 + c * 8);
        }
    };

    float acc[4][4][4];
    #pragma unroll
    for (int mi = 0; mi < 4; mi++)
        #pragma unroll
        for (int ni = 0; ni < 4; ni++)
            #pragma unroll
            for (int q = 0; q < 4; q++) acc[mi][ni][q] = 0.f;

    issue(0); asm volatile("cp.async.commit_group;" ::: "memory");
    issue(1); asm volatile("cp.async.commit_group;" ::: "memory");

    const int kIter = K / 32;
    for (int it = 0; it < kIter; it++) {
        asm volatile("cp.async.wait_group 1;" ::: "memory");
        __syncthreads();

        if (it + 2 < kIter) issue(it + 2);
        asm volatile("cp.async.commit_group;" ::: "memory");

        const __half* Ab = As + (it % PSTG) * STGH;
        const __half* Bb = Bs + (it % PSTG) * STGH;
        GEMM_STAGE_COMPUTE(Ab, Bb)
        __syncthreads();
    }

    #pragma unroll
    for (int mi = 0; mi < 4; mi++) {
        const int r0 = rowBase + wm * 64 + mi * 16 + g;
        #pragma unroll
        for (int ni = 0; ni < 4; ni++) {
            const int cidx = colBase + wn * 32 + ni * 8 + 2 * t;
            const float b0 = bias[cidx], b1 = bias[cidx + 1];
            *(float2*)(C + (size_t)r0 * N + cidx) =
                make_float2(acc[mi][ni][0] + b0, acc[mi][ni][1] + b1);
            *(float2*)(C + (size_t)(r0 + 8) * N + cidx) =
                make_float2(acc[mi][ni][2] + b0, acc[mi][ni][3] + b1);
        }
    }
}

// ---------------------------------------------------------------------------
// FA2 flash attention (unchanged structure from R12; launch_bounds hint)
// ---------------------------------------------------------------------------
#define ALD 72

__global__ __launch_bounds__(256, 2) void attn_fa2p_kernel(
    const __half* __restrict__ Q, const __half* __restrict__ K,
    const __half* __restrict__ V, __half* __restrict__ O)
{
    extern __shared__ __half sm[];
    __half* Qs = sm;                       // 128 x 72
    __half* Ks = Qs + 128 * ALD;           // 3 x (64 x 72)
    __half* Vs = Ks + 3 * 64 * ALD;        // 3 x (64 x 72)

    const int tid  = threadIdx.x;
    const int lane = tid & 31;
    const int wid  = tid >> 5;
    const int g    = lane >> 2;
    const int t    = lane & 3;
    const int rb   = wid * 16;

    const int bh = blockIdx.y;
    const int b  = bh / NHEAD;
    const int h  = bh % NHEAD;
    const int q0 = blockIdx.x * 128;

    const __half* Qg = Q + (size_t)b * SEQ * DMODEL + h * DHEAD;
    const __half* Kg = K + (size_t)b * SEQ * DMODEL + h * DHEAD;
    const __half* Vg = V + (size_t)b * SEQ * DMODEL + h * DHEAD;

    const int qr = lane & 15,                 qc = (lane >> 4) * 8;
    const int kr = (lane & 7) + ((lane >> 4) << 3), kc2 = ((lane >> 3) & 1) << 3;
    const int vr = (lane & 7) + (((lane >> 3) & 1) << 3), vc = (lane >> 4) << 3;

    #pragma unroll
    for (int i = 0; i < 4; i++) {
        const int ch = tid + i * 256;
        const int r = ch >> 3, c = ch & 7;
        *(uint4*)(Qs + r * ALD + c * 8) =
            *(const uint4*)(Qg + (size_t)(q0 + r) * DMODEL + c * 8);
    }

    auto issueKV = [&](int st) {
        if (st < SEQ / 64) {
            __half* kb = Ks + (st % 3) * 64 * ALD;
            __half* vb = Vs + (st % 3) * 64 * ALD;
            const int k0 = st * 64;
            #pragma unroll
            for (int i = 0; i < 2; i++) {
                const int ch = tid + i * 256;
                const int r = ch >> 3, c = ch & 7;
                cp_async16(kb + r * ALD + c * 8, Kg + (size_t)(k0 + r) * DMODEL + c * 8);
                cp_async16(vb + r * ALD + c * 8, Vg + (size_t)(k0 + r) * DMODEL + c * 8);
            }
        }
        asm volatile("cp.async.commit_group;" ::: "memory");
    };

    issueKV(0);
    issueKV(1);

    float o[8][4];
    #pragma unroll
    for (int nj = 0; nj < 8; nj++)
        #pragma unroll
        for (int q = 0; q < 4; q++) o[nj][q] = 0.f;
    float m0 = -1e30f, m1 = -1e30f, l0 = 0.f, l1 = 0.f;

    for (int ic = 0; ic < SEQ / 64; ic++) {
        asm volatile("cp.async.wait_group 1;" ::: "memory");
        __syncthreads();
        issueKV(ic + 2);

        const __half* Kb = Ks + (ic % 3) * 64 * ALD;
        const __half* Vb = Vs + (ic % 3) * 64 * ALD;

        float s[8][4];
        #pragma unroll
        for (int nj = 0; nj < 8; nj++)
            #pragma unroll
            for (int q = 0; q < 4; q++) s[nj][q] = 0.f;
        #pragma unroll
        for (int kk = 0; kk < 4; kk++) {
            uint32_t a0, a1, a2, a3;
            ldsm_x4(a0, a1, a2, a3,
                (uint32_t)__cvta_generic_to_shared(Qs + (rb + qr) * ALD + kk * 16 + qc));
            #pragma unroll
            for (int njp = 0; njp < 4; njp++) {
                uint32_t b0, b1, b2, b3;
                ldsm_x4(b0, b1, b2, b3,
                    (uint32_t)__cvta_generic_to_shared(Kb + (njp * 16 + kr) * ALD + kk * 16 + kc2));
                mma_f16(s[njp * 2    ], a0, a1, a2, a3, b0, b1);
                mma_f16(s[njp * 2 + 1], a0, a1, a2, a3, b2, b3);
            }
        }

        float tm0 = -1e30f, tm1 = -1e30f;
        #pragma unroll
        for (int nj = 0; nj < 8; nj++) {
            tm0 = fmaxf(tm0, fmaxf(s[nj][0], s[nj][1]));
            tm1 = fmaxf(tm1, fmaxf(s[nj][2], s[nj][3]));
        }
        tm0 = fmaxf(tm0, __shfl_xor_sync(0xffffffffu, tm0, 1));
        tm0 = fmaxf(tm0, __shfl_xor_sync(0xffffffffu, tm0, 2));
        tm1 = fmaxf(tm1, __shfl_xor_sync(0xffffffffu, tm1, 1));
        tm1 = fmaxf(tm1, __shfl_xor_sync(0xffffffffu, tm1, 2));
        const float m0n = fmaxf(m0, tm0);
        const float m1n = fmaxf(m1, tm1);
        const float sc0 = exp2f(m0 - m0n);
        const float sc1 = exp2f(m1 - m1n);
        float sum0 = 0.f, sum1 = 0.f;
        #pragma unroll
        for (int nj = 0; nj < 8; nj++) {
            s[nj][0] = exp2f(s[nj][0] - m0n); sum0 += s[nj][0];
            s[nj][1] = exp2f(s[nj][1] - m0n); sum0 += s[nj][1];
            s[nj][2] = exp2f(s[nj][2] - m1n); sum1 += s[nj][2];
            s[nj][3] = exp2f(s[nj][3] - m1n); sum1 += s[nj][3];
        }
        sum0 += __shfl_xor_sync(0xffffffffu, sum0, 1);
        sum0 += __shfl_xor_sync(0xffffffffu, sum0, 2);
        sum1 += __shfl_xor_sync(0xffffffffu, sum1, 1);
        sum1 += __shfl_xor_sync(0xffffffffu, sum1, 2);
        l0 = l0 * sc0 + sum0;  m0 = m0n;
        l1 = l1 * sc1 + sum1;  m1 = m1n;
        #pragma unroll
        for (int nj = 0; nj < 8; nj++) {
            o[nj][0] *= sc0; o[nj][1] *= sc0;
            o[nj][2] *= sc1; o[nj][3] *= sc1;
        }

        #pragma unroll
        for (int kcI = 0; kcI < 4; kcI++) {
            const uint32_t a0 = h2u(__floats2half2_rn(s[2 * kcI    ][0], s[2 * kcI    ][1]));
            const uint32_t a1 = h2u(__floats2half2_rn(s[2 * kcI    ][2], s[2 * kcI    ][3]));
            const uint32_t a2 = h2u(__floats2half2_rn(s[2 * kcI + 1][0], s[2 * kcI + 1][1]));
            const uint32_t a3 = h2u(__floats2half2_rn(s[2 * kcI + 1][2], s[2 * kcI + 1][3]));
            #pragma unroll
            for (int njp = 0; njp < 4; njp++) {
                uint32_t b0, b1, b2, b3;
                ldsm_x4_t(b0, b1, b2, b3,
                    (uint32_t)__cvta_generic_to_shared(Vb + (kcI * 16 + vr) * ALD + njp * 16 + vc));
                mma_f16(o[njp * 2    ], a0, a1, a2, a3, b0, b1);
                mma_f16(o[njp * 2 + 1], a0, a1, a2, a3, b2, b3);
            }
        }
    }

    const float li0 = 1.f / l0;
    const float li1 = 1.f / l1;
    __half* Og = O + (size_t)b * SEQ * DMODEL + h * DHEAD;
    #pragma unroll
    for (int nj = 0; nj < 8; nj++) {
        const int c = nj * 8 + 2 * t;
        *(uint32_t*)(Og + (size_t)(q0 + rb + g    ) * DMODEL + c) =
            h2u(__floats2half2_rn(o[nj][0] * li0, o[nj][1] * li0));
        *(uint32_t*)(Og + (size_t)(q0 + rb + g + 8) * DMODEL + c) =
            h2u(__floats2half2_rn(o[nj][2] * li1, o[nj][3] * li1));
    }
}

// ---------------------------------------------------------------------------
// Launch
// ---------------------------------------------------------------------------
extern "C" void kernel_launch(void* const* d_in, const int* in_sizes, int n_in,
                              void* d_out, int out_size)
{
    const float* z   = (const float*)d_in[0];
    const float* w_q = (const float*)d_in[1];
    const float* w_k = (const float*)d_in[2];
    const float* w_v = (const float*)d_in[3];
    const float* w_o = (const float*)d_in[4];
    const float* b_o = (const float*)d_in[5];
    float* out = (float*)d_out;

    const __half *zh, *Qh, *Kh, *Vh, *woh;
    __half* AOh;
    cudaGetSymbolAddress((void**)&zh,  g_zh);
    cudaGetSymbolAddress((void**)&Qh,  g_Qh);
    cudaGetSymbolAddress((void**)&Kh,  g_Kh);
    cudaGetSymbolAddress((void**)&Vh,  g_Vh);
    cudaGetSymbolAddress((void**)&woh, g_woh);
    cudaGetSymbolAddress((void**)&AOh, g_AOh);

    const int qkvSmem  = PSTG * 2 * STGH * (int)sizeof(__half);            // 61440
    const int attnSmem = (128 * ALD + 6 * 64 * ALD) * (int)sizeof(__half); // 73728
    static bool attrSet = false;
    if (!attrSet) {
        cudaFuncSetAttribute(gemm_qkv_kernel,
                             cudaFuncAttributeMaxDynamicSharedMemorySize, qkvSmem);
        cudaFuncSetAttribute(gemm_out_kernel,
                             cudaFuncAttributeMaxDynamicSharedMemorySize, qkvSmem);
        cudaFuncSetAttribute(attn_fa2p_kernel,
                             cudaFuncAttributeMaxDynamicSharedMemorySize, attnSmem);
        attrSet = true;
    }

    // 1. fp32 -> fp16 conversions
    const int nTot4 = NZ4 + 4 * NW4;
    cvt_all_kernel<<<(nTot4 + 255) / 256, 256>>>(z, w_q, w_k, w_v, w_o);

    // 2. fused QKV projections (Q pre-scaled by 1/8 * log2e)
    const float QSCALE = 0.125f * 1.4426950408889634f;
    gemm_qkv_kernel<<<dim3(DMODEL / 128, MTOT / 128, 3), 256, qkvSmem>>>(
        zh, MTOT, DMODEL, DMODEL, QSCALE);

    // 3. attention (fp16 out)
    attn_fa2p_kernel<<<dim3(SEQ / 128, BATCH * NHEAD), 256, attnSmem>>>(
        Qh, Kh, Vh, AOh);

    // 4. output projection (fp32 + bias out)
    gemm_out_kernel<<<dim3(DMODEL / 128, MTOT / 128), 256, qkvSmem>>>(
        AOh, woh, b_o, out, MTOT, DMODEL, DMODEL);
}

// round 16
// speedup vs baseline: 10.4698x; 1.0878x over previous
#include <cuda_runtime.h>
#include <cuda_fp16.h>
#include <math.h>
#include <stdint.h>

#define BATCH   8
#define SEQ     1024
#define DMODEL  768
#define NHEAD   12
#define DHEAD   64
#define MTOT    (BATCH * SEQ)   // 8192

// fp16 scratch
__device__ __half g_zh [MTOT * DMODEL];
__device__ __half g_wqh[DMODEL * DMODEL];
__device__ __half g_wkh[DMODEL * DMODEL];
__device__ __half g_wvh[DMODEL * DMODEL];
__device__ __half g_woh[DMODEL * DMODEL];
__device__ __half g_Qh [MTOT * DMODEL];
__device__ __half g_Kh [MTOT * DMODEL];
__device__ __half g_Vh [MTOT * DMODEL];
__device__ __half g_AOh[MTOT * DMODEL];

// ---------------------------------------------------------------------------
// Helpers
// ---------------------------------------------------------------------------
__device__ __forceinline__ void mma_f16(float c[4],
    uint32_t a0, uint32_t a1, uint32_t a2, uint32_t a3,
    uint32_t b0, uint32_t b1)
{
    asm volatile(
        "mma.sync.aligned.m16n8k16.row.col.f32.f16.f16.f32 "
        "{%0,%1,%2,%3}, {%4,%5,%6,%7}, {%8,%9}, {%0,%1,%2,%3};"
        : "+f"(c[0]), "+f"(c[1]), "+f"(c[2]), "+f"(c[3])
        : "r"(a0), "r"(a1), "r"(a2), "r"(a3), "r"(b0), "r"(b1));
}

__device__ __forceinline__ uint32_t h2u(__half2 h) {
    return *reinterpret_cast<uint32_t*>(&h);
}

__device__ __forceinline__ uint32_t h2exp2(uint32_t x) {
    uint32_t y;
    asm("ex2.approx.f16x2 %0, %1;" : "=r"(y) : "r"(x));
    return y;
}

__device__ __forceinline__ void cp_async16(void* smem_dst, const void* gmem_src) {
    uint32_t s = (uint32_t)__cvta_generic_to_shared(smem_dst);
    asm volatile("cp.async.cg.shared.global [%0], [%1], 16;\n"
                 :: "r"(s), "l"(gmem_src));
}

__device__ __forceinline__ void ldsm_x4(
    uint32_t& d0, uint32_t& d1, uint32_t& d2, uint32_t& d3, uint32_t addr)
{
    asm volatile("ldmatrix.sync.aligned.m8n8.x4.shared.b16 {%0,%1,%2,%3}, [%4];"
                 : "=r"(d0), "=r"(d1), "=r"(d2), "=r"(d3) : "r"(addr));
}

__device__ __forceinline__ void ldsm_x4_t(
    uint32_t& d0, uint32_t& d1, uint32_t& d2, uint32_t& d3, uint32_t addr)
{
    asm volatile("ldmatrix.sync.aligned.m8n8.x4.trans.shared.b16 {%0,%1,%2,%3}, [%4];"
                 : "=r"(d0), "=r"(d1), "=r"(d2), "=r"(d3) : "r"(addr));
}

__device__ __forceinline__ void ldsm_x2_t(
    uint32_t& d0, uint32_t& d1, uint32_t addr)
{
    asm volatile("ldmatrix.sync.aligned.m8n8.x2.trans.shared.b16 {%0,%1}, [%2];"
                 : "=r"(d0), "=r"(d1) : "r"(addr));
}

// ---------------------------------------------------------------------------
// fp32 -> fp16 conversion (z + 4 weights in one launch)
// ---------------------------------------------------------------------------
#define NZ4 ((MTOT * DMODEL) / 4)
#define NW4 ((DMODEL * DMODEL) / 4)

__global__ __launch_bounds__(256) void cvt_all_kernel(
    const float* __restrict__ z,  const float* __restrict__ wq,
    const float* __restrict__ wk, const float* __restrict__ wv,
    const float* __restrict__ wo)
{
    const int i = blockIdx.x * 256 + threadIdx.x;
    const float* src; __half* dst; int idx;
    if (i < NZ4)                { src = z;  dst = g_zh;  idx = i; }
    else if (i < NZ4 +   NW4)   { src = wq; dst = g_wqh; idx = i - NZ4; }
    else if (i < NZ4 + 2*NW4)   { src = wk; dst = g_wkh; idx = i - NZ4 - NW4; }
    else if (i < NZ4 + 3*NW4)   { src = wv; dst = g_wvh; idx = i - NZ4 - 2*NW4; }
    else if (i < NZ4 + 4*NW4)   { src = wo; dst = g_woh; idx = i - NZ4 - 3*NW4; }
    else return;
    float4 v = ((const float4*)src)[idx];
    uint2 p;
    p.x = h2u(__floats2half2_rn(v.x, v.y));
    p.y = h2u(__floats2half2_rn(v.z, v.w));
    ((uint2*)dst)[idx] = p;
}

// ---------------------------------------------------------------------------
// GEMM mainloop (128x128 tile, BK=64, 3-stage cp.async, ldmatrix frags).
// Stage stride 72 halfs (144B): LDSM phase rows hit word-banks 4r mod 32 ->
// conflict-free (same layout as attention).
// ---------------------------------------------------------------------------
#define GST   72
#define PSTG  3
#define STGH  (128 * GST)

#define GEMM_STAGE_COMPUTE(Ab, Bb)                                            \
    _Pragma("unroll")                                                         \
    for (int kk = 0; kk < 4; kk++) {                                          \
        uint32_t af[4][4], bf[4][2];                                          \
        _Pragma("unroll")                                                     \
        for (int mi = 0; mi < 4; mi++) {                                      \
            const int rb2 = wm * 64 + mi * 16;                                \
            ldsm_x4(af[mi][0], af[mi][1], af[mi][2], af[mi][3],               \
                (uint32_t)__cvta_generic_to_shared(                           \
                    (Ab) + (rb2 + ar) * GST + kk * 16 + ac));                 \
        }                                                                     \
        _Pragma("unroll")                                                     \
        for (int np = 0; np < 2; np++) {                                      \
            uint32_t b0, b1, b2, b3;                                          \
            ldsm_x4(b0, b1, b2, b3,                                           \
                (uint32_t)__cvta_generic_to_shared(                           \
                    (Bb) + (wn * 32 + np * 16 + br) * GST + kk * 16 + bc));   \
            bf[np * 2    ][0] = b0; bf[np * 2    ][1] = b1;                   \
            bf[np * 2 + 1][0] = b2; bf[np * 2 + 1][1] = b3;                   \
        }                                                                     \
        _Pragma("unroll")                                                     \
        for (int mi = 0; mi < 4; mi++)                                        \
            _Pragma("unroll")                                                 \
            for (int ni = 0; ni < 4; ni++)                                    \
                mma_f16(acc[mi][ni],                                          \
                        af[mi][0], af[mi][1], af[mi][2], af[mi][3],           \
                        bf[ni][0], bf[ni][1]);                                \
    }

#define GEMM_PROLOG_DECLS                                                     \
    const int tid  = threadIdx.x;                                             \
    const int lane = tid & 31;                                                \
    const int wid  = tid >> 5;                                                \
    const int g    = lane >> 2;                                               \
    const int t    = lane & 3;                                                \
    const int wm   = wid >> 2;                                                \
    const int wn   = wid & 3;                                                 \
    const int ar = lane & 15,                       ac = (lane >> 4) * 8;     \
    const int br = (lane & 7) + ((lane >> 4) << 3), bc = ((lane >> 3) & 1) << 3;

// issue one BK=64 stage: per operand 128 rows x 8 chunks(16B) = 1024 chunks
#define GEMM_ISSUE_BODY(st)                                                   \
    {                                                                         \
        const int buf = (st) % PSTG;                                          \
        const int k0  = (st) * 64;                                            \
        _Pragma("unroll")                                                     \
        for (int i = 0; i < 4; i++) {                                         \
            const int ch = tid + i * 256;                                     \
            const int r = ch >> 3, c = ch & 7;                                \
            cp_async16(As + buf * STGH + r * GST + c * 8,                     \
                       Ag + (size_t)r * K + k0 + c * 8);                      \
            cp_async16(Bs + buf * STGH + r * GST + c * 8,                     \
                       Bg + (size_t)r * K + k0 + c * 8);                      \
        }                                                                     \
    }

// ---------------------------------------------------------------------------
// Fused QKV GEMM (NT, fp16 in / fp16 out)
// ---------------------------------------------------------------------------
__global__ __launch_bounds__(256, 2) void gemm_qkv_kernel(
    const __half* __restrict__ A, int M, int N, int K, float qscale)
{
    extern __shared__ __half sh[];
    __half* As = sh;
    __half* Bs = sh + PSTG * STGH;

    const __half* B; __half* C; float outScale;
    if      (blockIdx.z == 0) { B = g_wqh; C = g_Qh; outScale = qscale; }
    else if (blockIdx.z == 1) { B = g_wkh; C = g_Kh; outScale = 1.f; }
    else                      { B = g_wvh; C = g_Vh; outScale = 1.f; }

    GEMM_PROLOG_DECLS

    const int rowBase = blockIdx.y * 128;
    const int colBase = blockIdx.x * 128;
    const __half* Ag = A + (size_t)rowBase * K;
    const __half* Bg = B + (size_t)colBase * K;

    float acc[4][4][4];
    #pragma unroll
    for (int mi = 0; mi < 4; mi++)
        #pragma unroll
        for (int ni = 0; ni < 4; ni++)
            #pragma unroll
            for (int q = 0; q < 4; q++) acc[mi][ni][q] = 0.f;

    GEMM_ISSUE_BODY(0) asm volatile("cp.async.commit_group;" ::: "memory");
    GEMM_ISSUE_BODY(1) asm volatile("cp.async.commit_group;" ::: "memory");

    const int kIter = K / 64;   // 12
    for (int it = 0; it < kIter; it++) {
        asm volatile("cp.async.wait_group 1;" ::: "memory");
        __syncthreads();

        if (it + 2 < kIter) GEMM_ISSUE_BODY(it + 2)
        asm volatile("cp.async.commit_group;" ::: "memory");

        const __half* Ab = As + (it % PSTG) * STGH;
        const __half* Bb = Bs + (it % PSTG) * STGH;
        GEMM_STAGE_COMPUTE(Ab, Bb)
        __syncthreads();
    }

    #pragma unroll
    for (int mi = 0; mi < 4; mi++) {
        const int r0 = rowBase + wm * 64 + mi * 16 + g;
        #pragma unroll
        for (int ni = 0; ni < 4; ni++) {
            const int cidx = colBase + wn * 32 + ni * 8 + 2 * t;
            *(uint32_t*)(C + (size_t)r0 * N + cidx) =
                h2u(__floats2half2_rn(acc[mi][ni][0] * outScale, acc[mi][ni][1] * outScale));
            *(uint32_t*)(C + (size_t)(r0 + 8) * N + cidx) =
                h2u(__floats2half2_rn(acc[mi][ni][2] * outScale, acc[mi][ni][3] * outScale));
        }
    }
}

// ---------------------------------------------------------------------------
// O projection GEMM (NT, fp16 in / fp32+bias out)
// ---------------------------------------------------------------------------
__global__ __launch_bounds__(256, 2) void gemm_out_kernel(
    const __half* __restrict__ A, const __half* __restrict__ B,
    const float* __restrict__ bias, float* __restrict__ C,
    int M, int N, int K)
{
    extern __shared__ __half sh[];
    __half* As = sh;
    __half* Bs = sh + PSTG * STGH;

    GEMM_PROLOG_DECLS

    const int rowBase = blockIdx.y * 128;
    const int colBase = blockIdx.x * 128;
    const __half* Ag = A + (size_t)rowBase * K;
    const __half* Bg = B + (size_t)colBase * K;

    float acc[4][4][4];
    #pragma unroll
    for (int mi = 0; mi < 4; mi++)
        #pragma unroll
        for (int ni = 0; ni < 4; ni++)
            #pragma unroll
            for (int q = 0; q < 4; q++) acc[mi][ni][q] = 0.f;

    GEMM_ISSUE_BODY(0) asm volatile("cp.async.commit_group;" ::: "memory");
    GEMM_ISSUE_BODY(1) asm volatile("cp.async.commit_group;" ::: "memory");

    const int kIter = K / 64;
    for (int it = 0; it < kIter; it++) {
        asm volatile("cp.async.wait_group 1;" ::: "memory");
        __syncthreads();

        if (it + 2 < kIter) GEMM_ISSUE_BODY(it + 2)
        asm volatile("cp.async.commit_group;" ::: "memory");

        const __half* Ab = As + (it % PSTG) * STGH;
        const __half* Bb = Bs + (it % PSTG) * STGH;
        GEMM_STAGE_COMPUTE(Ab, Bb)
        __syncthreads();
    }

    #pragma unroll
    for (int mi = 0; mi < 4; mi++) {
        const int r0 = rowBase + wm * 64 + mi * 16 + g;
        #pragma unroll
        for (int ni = 0; ni < 4; ni++) {
            const int cidx = colBase + wn * 32 + ni * 8 + 2 * t;
            const float b0 = bias[cidx], b1 = bias[cidx + 1];
            *(float2*)(C + (size_t)r0 * N + cidx) =
                make_float2(acc[mi][ni][0] + b0, acc[mi][ni][1] + b1);
            *(float2*)(C + (size_t)(r0 + 8) * N + cidx) =
                make_float2(acc[mi][ni][2] + b0, acc[mi][ni][3] + b1);
        }
    }
}

// ---------------------------------------------------------------------------
// FA2 flash attention: fp16 in/out, 3-deep K/V cp.async pipeline, ldmatrix.
// Softmax: half2 ex2 (P produced directly as fp16 A-frags); the normalizer l
// is accumulated by the MMA itself via a ones-column in V's smem pad (col 64)
// -> one extra ldsm.x2.trans + MMA per k-step, no per-chunk sum reduction.
// ---------------------------------------------------------------------------
#define ALD 72

__global__ __launch_bounds__(256, 2) void attn_fa2p_kernel(
    const __half* __restrict__ Q, const __half* __restrict__ K,
    const __half* __restrict__ V, __half* __restrict__ O)
{
    extern __shared__ __half sm[];
    __half* Qs = sm;                       // 128 x 72
    __half* Ks = Qs + 128 * ALD;           // 3 x (64 x 72)
    __half* Vs = Ks + 3 * 64 * ALD;        // 3 x (64 x 72); col 64 = ones

    const int tid  = threadIdx.x;
    const int lane = tid & 31;
    const int wid  = tid >> 5;
    const int g    = lane >> 2;
    const int t    = lane & 3;
    const int rb   = wid * 16;

    const int bh = blockIdx.y;
    const int b  = bh / NHEAD;
    const int h  = bh % NHEAD;
    const int q0 = blockIdx.x * 128;

    const __half* Qg = Q + (size_t)b * SEQ * DMODEL + h * DHEAD;
    const __half* Kg = K + (size_t)b * SEQ * DMODEL + h * DHEAD;
    const __half* Vg = V + (size_t)b * SEQ * DMODEL + h * DHEAD;

    const int qr = lane & 15,                 qc = (lane >> 4) * 8;
    const int kr = (lane & 7) + ((lane >> 4) << 3), kc2 = ((lane >> 3) & 1) << 3;
    const int vr = (lane & 7) + (((lane >> 3) & 1) << 3), vc = (lane >> 4) << 3;
    const int ur = lane & 15;   // ldsm.x2 row (lanes 0..15 used)

    // Q tile
    #pragma unroll
    for (int i = 0; i < 4; i++) {
        const int ch = tid + i * 256;
        const int r = ch >> 3, c = ch & 7;
        *(uint4*)(Qs + r * ALD + c * 8) =
            *(const uint4*)(Qg + (size_t)(q0 + r) * DMODEL + c * 8);
    }
    // ones-column init in V pad (cols 64..71): {1,0,0,0,0,0,0,0}
    if (tid < 192) {
        const int buf = tid >> 6, r = tid & 63;
        __half* p = Vs + buf * 64 * ALD + r * ALD + 64;
        *(uint2*)(p)     = make_uint2(0x00003C00u, 0u);
        *(uint2*)(p + 4) = make_uint2(0u, 0u);
    }

    auto issueKV = [&](int st) {
        if (st < SEQ / 64) {
            __half* kb = Ks + (st % 3) * 64 * ALD;
            __half* vb = Vs + (st % 3) * 64 * ALD;
            const int k0 = st * 64;
            #pragma unroll
            for (int i = 0; i < 2; i++) {
                const int ch = tid + i * 256;
                const int r = ch >> 3, c = ch & 7;
                cp_async16(kb + r * ALD + c * 8, Kg + (size_t)(k0 + r) * DMODEL + c * 8);
                cp_async16(vb + r * ALD + c * 8, Vg + (size_t)(k0 + r) * DMODEL + c * 8);
            }
        }
        asm volatile("cp.async.commit_group;" ::: "memory");
    };

    issueKV(0);
    issueKV(1);

    float o[8][4], osum[4];
    #pragma unroll
    for (int nj = 0; nj < 8; nj++)
        #pragma unroll
        for (int q = 0; q < 4; q++) o[nj][q] = 0.f;
    #pragma unroll
    for (int q = 0; q < 4; q++) osum[q] = 0.f;
    float m0 = -1e30f, m1 = -1e30f;

    for (int ic = 0; ic < SEQ / 64; ic++) {
        asm volatile("cp.async.wait_group 1;" ::: "memory");
        __syncthreads();
        issueKV(ic + 2);

        const __half* Kb = Ks + (ic % 3) * 64 * ALD;
        const __half* Vb = Vs + (ic % 3) * 64 * ALD;

        // S = Q @ K^T (log2 domain)
        float s[8][4];
        #pragma unroll
        for (int nj = 0; nj < 8; nj++)
            #pragma unroll
            for (int q = 0; q < 4; q++) s[nj][q] = 0.f;
        #pragma unroll
        for (int kk = 0; kk < 4; kk++) {
            uint32_t a0, a1, a2, a3;
            ldsm_x4(a0, a1, a2, a3,
                (uint32_t)__cvta_generic_to_shared(Qs + (rb + qr) * ALD + kk * 16 + qc));
            #pragma unroll
            for (int njp = 0; njp < 4; njp++) {
                uint32_t b0, b1, b2, b3;
                ldsm_x4(b0, b1, b2, b3,
                    (uint32_t)__cvta_generic_to_shared(Kb + (njp * 16 + kr) * ALD + kk * 16 + kc2));
                mma_f16(s[njp * 2    ], a0, a1, a2, a3, b0, b1);
                mma_f16(s[njp * 2 + 1], a0, a1, a2, a3, b2, b3);
            }
        }

        // online max + half2 probabilities
        float tm0 = -1e30f, tm1 = -1e30f;
        #pragma unroll
        for (int nj = 0; nj < 8; nj++) {
            tm0 = fmaxf(tm0, fmaxf(s[nj][0], s[nj][1]));
            tm1 = fmaxf(tm1, fmaxf(s[nj][2], s[nj][3]));
        }
        tm0 = fmaxf(tm0, __shfl_xor_sync(0xffffffffu, tm0, 1));
        tm0 = fmaxf(tm0, __shfl_xor_sync(0xffffffffu, tm0, 2));
        tm1 = fmaxf(tm1, __shfl_xor_sync(0xffffffffu, tm1, 1));
        tm1 = fmaxf(tm1, __shfl_xor_sync(0xffffffffu, tm1, 2));
        const float m0n = fmaxf(m0, tm0);
        const float m1n = fmaxf(m1, tm1);
        const float sc0 = exp2f(m0 - m0n);
        const float sc1 = exp2f(m1 - m1n);
        m0 = m0n; m1 = m1n;

        uint32_t p01[8], p23[8];
        #pragma unroll
        for (int nj = 0; nj < 8; nj++) {
            p01[nj] = h2exp2(h2u(__floats2half2_rn(s[nj][0] - m0n, s[nj][1] - m0n)));
            p23[nj] = h2exp2(h2u(__floats2half2_rn(s[nj][2] - m1n, s[nj][3] - m1n)));
        }

        // rescale accumulators (osum follows the same recurrence as l)
        #pragma unroll
        for (int nj = 0; nj < 8; nj++) {
            o[nj][0] *= sc0; o[nj][1] *= sc0;
            o[nj][2] *= sc1; o[nj][3] *= sc1;
        }
        osum[0] *= sc0; osum[1] *= sc0; osum[2] *= sc1; osum[3] *= sc1;

        // O += P @ V ; osum += P @ ones
        #pragma unroll
        for (int kcI = 0; kcI < 4; kcI++) {
            const uint32_t a0 = p01[2 * kcI    ];
            const uint32_t a1 = p23[2 * kcI    ];
            const uint32_t a2 = p01[2 * kcI + 1];
            const uint32_t a3 = p23[2 * kcI + 1];
            #pragma unroll
            for (int njp = 0; njp < 4; njp++) {
                uint32_t b0, b1, b2, b3;
                ldsm_x4_t(b0, b1, b2, b3,
                    (uint32_t)__cvta_generic_to_shared(Vb + (kcI * 16 + vr) * ALD + njp * 16 + vc));
                mma_f16(o[njp * 2    ], a0, a1, a2, a3, b0, b1);
                mma_f16(o[njp * 2 + 1], a0, a1, a2, a3, b2, b3);
            }
            uint32_t u0, u1;
            ldsm_x2_t(u0, u1,
                (uint32_t)__cvta_generic_to_shared(Vb + (kcI * 16 + ur) * ALD + 64));
            mma_f16(osum, a0, a1, a2, a3, u0, u1);
        }
    }

    // l = ones-column sums (held by t==0 lanes at col 64)
    const float l0 = __shfl_sync(0xffffffffu, osum[0], lane & ~3);
    const float l1 = __shfl_sync(0xffffffffu, osum[2], lane & ~3);
    const float li0 = 1.f / l0;
    const float li1 = 1.f / l1;
    __half* Og = O + (size_t)b * SEQ * DMODEL + h * DHEAD;
    #pragma unroll
    for (int nj = 0; nj < 8; nj++) {
        const int c = nj * 8 + 2 * t;
        *(uint32_t*)(Og + (size_t)(q0 + rb + g    ) * DMODEL + c) =
            h2u(__floats2half2_rn(o[nj][0] * li0, o[nj][1] * li0));
        *(uint32_t*)(Og + (size_t)(q0 + rb + g + 8) * DMODEL + c) =
            h2u(__floats2half2_rn(o[nj][2] * li1, o[nj][3] * li1));
    }
}

// ---------------------------------------------------------------------------
// Launch
// ---------------------------------------------------------------------------
extern "C" void kernel_launch(void* const* d_in, const int* in_sizes, int n_in,
                              void* d_out, int out_size)
{
    const float* z   = (const float*)d_in[0];
    const float* w_q = (const float*)d_in[1];
    const float* w_k = (const float*)d_in[2];
    const float* w_v = (const float*)d_in[3];
    const float* w_o = (const float*)d_in[4];
    const float* b_o = (const float*)d_in[5];
    float* out = (float*)d_out;

    const __half *zh, *Qh, *Kh, *Vh, *woh;
    __half* AOh;
    cudaGetSymbolAddress((void**)&zh,  g_zh);
    cudaGetSymbolAddress((void**)&Qh,  g_Qh);
    cudaGetSymbolAddress((void**)&Kh,  g_Kh);
    cudaGetSymbolAddress((void**)&Vh,  g_Vh);
    cudaGetSymbolAddress((void**)&woh, g_woh);
    cudaGetSymbolAddress((void**)&AOh, g_AOh);

    const int gemmSmem = PSTG * 2 * STGH * (int)sizeof(__half);            // 110592
    const int attnSmem = (128 * ALD + 6 * 64 * ALD) * (int)sizeof(__half); // 73728
    static bool attrSet = false;
    if (!attrSet) {
        cudaFuncSetAttribute(gemm_qkv_kernel,
                             cudaFuncAttributeMaxDynamicSharedMemorySize, gemmSmem);
        cudaFuncSetAttribute(gemm_out_kernel,
                             cudaFuncAttributeMaxDynamicSharedMemorySize, gemmSmem);
        cudaFuncSetAttribute(attn_fa2p_kernel,
                             cudaFuncAttributeMaxDynamicSharedMemorySize, attnSmem);
        attrSet = true;
    }

    // 1. fp32 -> fp16 conversions
    const int nTot4 = NZ4 + 4 * NW4;
    cvt_all_kernel<<<(nTot4 + 255) / 256, 256>>>(z, w_q, w_k, w_v, w_o);

    // 2. fused QKV projections (Q pre-scaled by 1/8 * log2e)
    const float QSCALE = 0.125f * 1.4426950408889634f;
    gemm_qkv_kernel<<<dim3(DMODEL / 128, MTOT / 128, 3), 256, gemmSmem>>>(
        zh, MTOT, DMODEL, DMODEL, QSCALE);

    // 3. attention (fp16 out)
    attn_fa2p_kernel<<<dim3(SEQ / 128, BATCH * NHEAD), 256, attnSmem>>>(
        Qh, Kh, Vh, AOh);

    // 4. output projection (fp32 + bias out)
    gemm_out_kernel<<<dim3(DMODEL / 128, MTOT / 128), 256, gemmSmem>>>(
        AOh, woh, b_o, out, MTOT, DMODEL, DMODEL);
}